// round 1
// baseline (speedup 1.0000x reference)
#include <cuda_runtime.h>
#include <cstdint>

// ---------------------------------------------------------------------------
// LocalAttention: x(2,2048,1024) -> qkv gemm -> 27-neighbor local attention
//                 (8x16x16 token grid, 16 heads x 64 dim) -> out-proj gemm.
// Round 1: fp32 SGEMM (NT) + warp-per-head attention kernel.
// ---------------------------------------------------------------------------

#define TOKEN_T 8
#define TOKEN_HH 16
#define TOKEN_WW 16
#define NTOK   2048
#define BATCH  2
#define HID    1024
#define NHEAD  16
#define HDIM   64
#define M_TOT  (BATCH * NTOK)   // 4096

// Scratch (device globals: allocation-free per harness rules)
__device__ float g_qkv[(size_t)M_TOT * 3 * HID];   // 50.3 MB
__device__ float g_att[(size_t)M_TOT * HID];       // 16.8 MB

// ---------------------------------------------------------------------------
// SGEMM (NT): C[M,N] = A[M,K] * B[N,K]^T, all row-major, K % 8 == 0,
// M % 128 == 0, N % 128 == 0. 128x128 block tile, 8x8 per thread, BK=8.
// ---------------------------------------------------------------------------
template <int BM, int BN, int BK, int TM, int TN>
__global__ __launch_bounds__(256, 2)
void sgemm_nt(const float* __restrict__ A, const float* __restrict__ B,
              float* __restrict__ C, int M, int N, int K) {
    __shared__ float As[BK][BM];
    __shared__ float Bs[BK][BN];

    const int tid = threadIdx.x;
    const int tx = tid % (BN / TN);   // 0..15
    const int ty = tid / (BN / TN);   // 0..15
    const int loadRow = tid >> 1;         // 0..127
    const int loadCol = (tid & 1) * 4;    // 0 or 4

    const float* Ab = A + (size_t)blockIdx.y * BM * K;
    const float* Bb = B + (size_t)blockIdx.x * BN * K;

    float acc[TM][TN];
#pragma unroll
    for (int i = 0; i < TM; i++)
#pragma unroll
        for (int j = 0; j < TN; j++) acc[i][j] = 0.0f;

    for (int k0 = 0; k0 < K; k0 += BK) {
        float4 a4 = *reinterpret_cast<const float4*>(Ab + (size_t)loadRow * K + k0 + loadCol);
        float4 b4 = *reinterpret_cast<const float4*>(Bb + (size_t)loadRow * K + k0 + loadCol);
        As[loadCol + 0][loadRow] = a4.x;
        As[loadCol + 1][loadRow] = a4.y;
        As[loadCol + 2][loadRow] = a4.z;
        As[loadCol + 3][loadRow] = a4.w;
        Bs[loadCol + 0][loadRow] = b4.x;
        Bs[loadCol + 1][loadRow] = b4.y;
        Bs[loadCol + 2][loadRow] = b4.z;
        Bs[loadCol + 3][loadRow] = b4.w;
        __syncthreads();

#pragma unroll
        for (int kk = 0; kk < BK; kk++) {
            float af[TM], bf[TN];
#pragma unroll
            for (int i = 0; i < TM; i += 4) {
                float4 t = *reinterpret_cast<const float4*>(&As[kk][ty * TM + i]);
                af[i] = t.x; af[i + 1] = t.y; af[i + 2] = t.z; af[i + 3] = t.w;
            }
#pragma unroll
            for (int j = 0; j < TN; j += 4) {
                float4 t = *reinterpret_cast<const float4*>(&Bs[kk][tx * TN + j]);
                bf[j] = t.x; bf[j + 1] = t.y; bf[j + 2] = t.z; bf[j + 3] = t.w;
            }
#pragma unroll
            for (int i = 0; i < TM; i++)
#pragma unroll
                for (int j = 0; j < TN; j++)
                    acc[i][j] = fmaf(af[i], bf[j], acc[i][j]);
        }
        __syncthreads();
    }

    float* Cb = C + ((size_t)blockIdx.y * BM + ty * TM) * N + (size_t)blockIdx.x * BN + tx * TN;
#pragma unroll
    for (int i = 0; i < TM; i++) {
#pragma unroll
        for (int j = 0; j < TN; j += 4) {
            float4 t = make_float4(acc[i][j], acc[i][j + 1], acc[i][j + 2], acc[i][j + 3]);
            *reinterpret_cast<float4*>(Cb + (size_t)i * N + j) = t;
        }
    }
}

// ---------------------------------------------------------------------------
// Local attention: one block per token (4096 blocks), one warp per head (16
// warps). Each lane owns dims {lane, lane+32} of the 64-dim head.
// IMPORTANT: reference zero-pads the 3x3x3 neighborhood, so out-of-bounds
// neighbors contribute logit 0 (participating in softmax!) and value 0.
// ---------------------------------------------------------------------------
__global__ __launch_bounds__(512)
void local_attn(const float* __restrict__ qkv, float* __restrict__ att) {
    const int tokenIdx = blockIdx.x;           // 0..4095 (b*2048 + n)
    const int b = tokenIdx / NTOK;
    const int n = tokenIdx % NTOK;
    const int t  = n / (TOKEN_HH * TOKEN_WW);
    const int hy = (n / TOKEN_WW) % TOKEN_HH;
    const int wx = n % TOKEN_WW;
    const int head = threadIdx.x >> 5;         // 0..15
    const int lane = threadIdx.x & 31;

    const float* qptr = qkv + (size_t)tokenIdx * (3 * HID) + head * HDIM;
    const float q0 = qptr[lane];
    const float q1 = qptr[lane + 32];

    float s[27];
    int   nidx[27];
    bool  valid[27];

#pragma unroll
    for (int j = 0; j < 27; j++) {
        const int dt = j / 9 - 1;
        const int dh = (j / 3) % 3 - 1;
        const int dw = j % 3 - 1;
        const int tt = t + dt, hh = hy + dh, ww = wx + dw;
        const bool v = (tt >= 0) && (tt < TOKEN_T) &&
                       (hh >= 0) && (hh < TOKEN_HH) &&
                       (ww >= 0) && (ww < TOKEN_WW);
        valid[j] = v;
        const int nn = (tt * TOKEN_HH + hh) * TOKEN_WW + ww;
        nidx[j] = nn;
        float part = 0.0f;
        if (v) {
            const float* kptr = qkv + ((size_t)(b * NTOK + nn)) * (3 * HID) + HID + head * HDIM;
            part = q0 * kptr[lane] + q1 * kptr[lane + 32];
        }
        // butterfly reduce -> every lane holds the full 64-dim dot
#pragma unroll
        for (int off = 16; off; off >>= 1)
            part += __shfl_xor_sync(0xffffffffu, part, off);
        s[j] = v ? part * 0.125f : 0.0f;   // scale = 64^-0.5; padded logits are 0
    }

    float mx = s[0];
#pragma unroll
    for (int j = 1; j < 27; j++) mx = fmaxf(mx, s[j]);
    float denom = 0.0f;
#pragma unroll
    for (int j = 0; j < 27; j++) { s[j] = __expf(s[j] - mx); denom += s[j]; }
    const float inv = 1.0f / denom;

    float o0 = 0.0f, o1 = 0.0f;
#pragma unroll
    for (int j = 0; j < 27; j++) {
        if (valid[j]) {
            const float* vptr = qkv + ((size_t)(b * NTOK + nidx[j])) * (3 * HID) + 2 * HID + head * HDIM;
            const float w = s[j] * inv;
            o0 = fmaf(w, vptr[lane], o0);
            o1 = fmaf(w, vptr[lane + 32], o1);
        }
    }

    float* optr = att + (size_t)tokenIdx * HID + head * HDIM;
    optr[lane] = o0;
    optr[lane + 32] = o1;
}

// ---------------------------------------------------------------------------
// Launch
// ---------------------------------------------------------------------------
extern "C" void kernel_launch(void* const* d_in, const int* in_sizes, int n_in,
                              void* d_out, int out_size) {
    const float* x     = (const float*)d_in[0];  // (2, 2048, 1024)
    const float* w_qkv = (const float*)d_in[1];  // (3072, 1024)
    const float* w_out = (const float*)d_in[2];  // (1024, 1024)
    float* out = (float*)d_out;                  // (2, 2048, 1024)

    float* qkv = nullptr;
    float* att = nullptr;
    cudaGetSymbolAddress((void**)&qkv, g_qkv);
    cudaGetSymbolAddress((void**)&att, g_att);

    // 1) QKV: (4096,3072) = x(4096,1024) * w_qkv(3072,1024)^T
    {
        dim3 grid(3 * HID / 128, M_TOT / 128);
        sgemm_nt<128, 128, 8, 8, 8><<<grid, 256>>>(x, w_qkv, qkv, M_TOT, 3 * HID, HID);
    }

    // 2) Local attention
    local_attn<<<M_TOT, 512>>>(qkv, att);

    // 3) Out-proj: (4096,1024) = att(4096,1024) * w_out(1024,1024)^T
    {
        dim3 grid(HID / 128, M_TOT / 128);
        sgemm_nt<128, 128, 8, 8, 8><<<grid, 256>>>(att, w_out, out, M_TOT, HID, HID);
    }
}

// round 2
// speedup vs baseline: 1.8698x; 1.8698x over previous
#include <cuda_runtime.h>
#include <cuda_bf16.h>
#include <cstdint>

// ---------------------------------------------------------------------------
// LocalAttention: x(2,2048,1024) -> qkv gemm -> 27-neighbor local attention
//                 (8x16x16 grid, 16 heads x 64 dim) -> out-proj gemm.
// Round 2: bf16 split-precision (hi/lo, 3-product) tensor-core GEMMs via
//          mma.sync.m16n8k16 + ldmatrix; fp32-accurate (~1e-5 rel err).
// ---------------------------------------------------------------------------

#define TOKEN_T  8
#define TOKEN_HH 16
#define TOKEN_WW 16
#define NTOK     2048
#define BATCH    2
#define HID      1024
#define NHEAD    16
#define HDIM     64
#define M_TOT    (BATCH * NTOK)   // 4096

// Scratch (device globals: allocation-free per harness rules)
__device__ float g_qkv[(size_t)M_TOT * 3 * HID];   // fp32 qkv
__device__ float g_att[(size_t)M_TOT * HID];       // fp32 attention out

__device__ __nv_bfloat16 g_xhi[(size_t)M_TOT * HID];
__device__ __nv_bfloat16 g_xlo[(size_t)M_TOT * HID];
__device__ __nv_bfloat16 g_wqhi[(size_t)3 * HID * HID];
__device__ __nv_bfloat16 g_wqlo[(size_t)3 * HID * HID];
__device__ __nv_bfloat16 g_wohi[(size_t)HID * HID];
__device__ __nv_bfloat16 g_wolo[(size_t)HID * HID];
__device__ __nv_bfloat16 g_ahi[(size_t)M_TOT * HID];
__device__ __nv_bfloat16 g_alo[(size_t)M_TOT * HID];

// ---------------------------------------------------------------------------
// fp32 -> (bf16 hi, bf16 lo) split.  lo = bf16(v - float(hi)).
// ---------------------------------------------------------------------------
__global__ void cvt_split(const float4* __restrict__ in,
                          uint2* __restrict__ hi, uint2* __restrict__ lo,
                          int n4) {
    int i = blockIdx.x * blockDim.x + threadIdx.x;
    if (i >= n4) return;
    float4 v = in[i];
    __nv_bfloat16 h0 = __float2bfloat16(v.x);
    __nv_bfloat16 h1 = __float2bfloat16(v.y);
    __nv_bfloat16 h2 = __float2bfloat16(v.z);
    __nv_bfloat16 h3 = __float2bfloat16(v.w);
    __nv_bfloat16 l0 = __float2bfloat16(v.x - __bfloat162float(h0));
    __nv_bfloat16 l1 = __float2bfloat16(v.y - __bfloat162float(h1));
    __nv_bfloat16 l2 = __float2bfloat16(v.z - __bfloat162float(h2));
    __nv_bfloat16 l3 = __float2bfloat16(v.w - __bfloat162float(h3));
    __nv_bfloat162 ha = __nv_bfloat162(h0, h1), hb = __nv_bfloat162(h2, h3);
    __nv_bfloat162 la = __nv_bfloat162(l0, l1), lb = __nv_bfloat162(l2, l3);
    uint2 H, L;
    H.x = *reinterpret_cast<uint32_t*>(&ha);
    H.y = *reinterpret_cast<uint32_t*>(&hb);
    L.x = *reinterpret_cast<uint32_t*>(&la);
    L.y = *reinterpret_cast<uint32_t*>(&lb);
    hi[i] = H;
    lo[i] = L;
}

// ---------------------------------------------------------------------------
// Tensor-core GEMM (NT): C[M,N] = A[M,K] * B[N,K]^T (both K-contiguous),
// 3-product bf16 split accumulation in fp32.
// Tile: 128x128x32, 256 threads (8 warps, 2x4), warp tile 64x32 (4x4 mmas).
// ---------------------------------------------------------------------------
#define BKP 40   // padded smem K stride (halves): conflict-free for ldmatrix

__device__ __forceinline__ void ldsm4(uint32_t* r, uint32_t addr) {
    asm volatile("ldmatrix.sync.aligned.m8n8.x4.shared.b16 {%0,%1,%2,%3},[%4];\n"
                 : "=r"(r[0]), "=r"(r[1]), "=r"(r[2]), "=r"(r[3]) : "r"(addr));
}
__device__ __forceinline__ void ldsm2(uint32_t* r, uint32_t addr) {
    asm volatile("ldmatrix.sync.aligned.m8n8.x2.shared.b16 {%0,%1},[%2];\n"
                 : "=r"(r[0]), "=r"(r[1]) : "r"(addr));
}
__device__ __forceinline__ void mma16816(float* d, const uint32_t* a, const uint32_t* b) {
    asm volatile("mma.sync.aligned.m16n8k16.row.col.f32.bf16.bf16.f32 "
                 "{%0,%1,%2,%3},{%4,%5,%6,%7},{%8,%9},{%0,%1,%2,%3};\n"
                 : "+f"(d[0]), "+f"(d[1]), "+f"(d[2]), "+f"(d[3])
                 : "r"(a[0]), "r"(a[1]), "r"(a[2]), "r"(a[3]),
                   "r"(b[0]), "r"(b[1]));
}

__global__ __launch_bounds__(256, 2)
void gemm_bf16x3(const __nv_bfloat16* __restrict__ Ahi,
                 const __nv_bfloat16* __restrict__ Alo,
                 const __nv_bfloat16* __restrict__ Bhi,
                 const __nv_bfloat16* __restrict__ Blo,
                 float* __restrict__ C, int M, int N, int K) {
    __shared__ __align__(16) __nv_bfloat16 As[2][128][BKP];  // [hi/lo][m][k]
    __shared__ __align__(16) __nv_bfloat16 Bs[2][128][BKP];  // [hi/lo][n][k]

    const int tid  = threadIdx.x;
    const int lane = tid & 31;
    const int warp = tid >> 5;
    const int wm = (warp >> 2) * 64;   // warp M offset in tile
    const int wn = (warp & 3) * 32;    // warp N offset in tile
    const int mrow0 = blockIdx.y * 128;
    const int ncol0 = blockIdx.x * 128;

    float acc[4][4][4];
#pragma unroll
    for (int mi = 0; mi < 4; mi++)
#pragma unroll
        for (int ni = 0; ni < 4; ni++)
#pragma unroll
            for (int r = 0; r < 4; r++) acc[mi][ni][r] = 0.0f;

    // global load mapping: thread t loads row (t>>1), 16 halves at col (t&1)*16
    const int lr = tid >> 1;
    const int lc = (tid & 1) * 16;
    const __nv_bfloat16* pAh = Ahi + (size_t)(mrow0 + lr) * K + lc;
    const __nv_bfloat16* pAl = Alo + (size_t)(mrow0 + lr) * K + lc;
    const __nv_bfloat16* pBh = Bhi + (size_t)(ncol0 + lr) * K + lc;
    const __nv_bfloat16* pBl = Blo + (size_t)(ncol0 + lr) * K + lc;

    // per-lane ldmatrix smem addresses (computed once; k offset added in loop)
    const int a_row = (lane & 15);
    const int a_kof = (lane >> 4) << 3;
    const int b_row = (lane & 7);
    const int b_kof = (lane & 8);   // 0 or 8

    for (int k0 = 0; k0 < K; k0 += 32) {
        uint4 v;
        v = *reinterpret_cast<const uint4*>(pAh + k0);
        *reinterpret_cast<uint4*>(&As[0][lr][lc]) = v;
        v = *reinterpret_cast<const uint4*>(pAh + k0 + 8);
        *reinterpret_cast<uint4*>(&As[0][lr][lc + 8]) = v;
        v = *reinterpret_cast<const uint4*>(pAl + k0);
        *reinterpret_cast<uint4*>(&As[1][lr][lc]) = v;
        v = *reinterpret_cast<const uint4*>(pAl + k0 + 8);
        *reinterpret_cast<uint4*>(&As[1][lr][lc + 8]) = v;
        v = *reinterpret_cast<const uint4*>(pBh + k0);
        *reinterpret_cast<uint4*>(&Bs[0][lr][lc]) = v;
        v = *reinterpret_cast<const uint4*>(pBh + k0 + 8);
        *reinterpret_cast<uint4*>(&Bs[0][lr][lc + 8]) = v;
        v = *reinterpret_cast<const uint4*>(pBl + k0);
        *reinterpret_cast<uint4*>(&Bs[1][lr][lc]) = v;
        v = *reinterpret_cast<const uint4*>(pBl + k0 + 8);
        *reinterpret_cast<uint4*>(&Bs[1][lr][lc + 8]) = v;
        __syncthreads();

#pragma unroll
        for (int kk = 0; kk < 32; kk += 16) {
            uint32_t a[4][4];
            uint32_t bh[4][2], bl[4][2];
            // A hi fragments
#pragma unroll
            for (int mi = 0; mi < 4; mi++) {
                uint32_t ad = (uint32_t)__cvta_generic_to_shared(
                    &As[0][wm + mi * 16 + a_row][kk + a_kof]);
                ldsm4(a[mi], ad);
            }
            // B hi + lo fragments
#pragma unroll
            for (int ni = 0; ni < 4; ni++) {
                uint32_t bdh = (uint32_t)__cvta_generic_to_shared(
                    &Bs[0][wn + ni * 8 + b_row][kk + b_kof]);
                uint32_t bdl = (uint32_t)__cvta_generic_to_shared(
                    &Bs[1][wn + ni * 8 + b_row][kk + b_kof]);
                ldsm2(bh[ni], bdh);
                ldsm2(bl[ni], bdl);
            }
            // pass 1: hi*hi ; pass 2: hi*lo
#pragma unroll
            for (int mi = 0; mi < 4; mi++)
#pragma unroll
                for (int ni = 0; ni < 4; ni++) {
                    mma16816(acc[mi][ni], a[mi], bh[ni]);
                    mma16816(acc[mi][ni], a[mi], bl[ni]);
                }
            // A lo fragments (reuse regs), pass 3: lo*hi
#pragma unroll
            for (int mi = 0; mi < 4; mi++) {
                uint32_t ad = (uint32_t)__cvta_generic_to_shared(
                    &As[1][wm + mi * 16 + a_row][kk + a_kof]);
                ldsm4(a[mi], ad);
            }
#pragma unroll
            for (int mi = 0; mi < 4; mi++)
#pragma unroll
                for (int ni = 0; ni < 4; ni++)
                    mma16816(acc[mi][ni], a[mi], bh[ni]);
        }
        __syncthreads();
    }

    // epilogue: d0,d1 -> (m, n..n+1); d2,d3 -> (m+8, n..n+1)
    const int em = mrow0 + wm + (lane >> 2);
    const int en = ncol0 + wn + (lane & 3) * 2;
#pragma unroll
    for (int mi = 0; mi < 4; mi++) {
#pragma unroll
        for (int ni = 0; ni < 4; ni++) {
            float* c0 = C + (size_t)(em + mi * 16) * N + en + ni * 8;
            float* c1 = C + (size_t)(em + mi * 16 + 8) * N + en + ni * 8;
            *reinterpret_cast<float2*>(c0) = make_float2(acc[mi][ni][0], acc[mi][ni][1]);
            *reinterpret_cast<float2*>(c1) = make_float2(acc[mi][ni][2], acc[mi][ni][3]);
        }
    }
}

// ---------------------------------------------------------------------------
// Local attention (unchanged from round 1): one block per token, one warp per
// head; reference zero-pads, so OOB neighbors contribute logit 0 (in softmax)
// and value 0.
// ---------------------------------------------------------------------------
__global__ __launch_bounds__(512)
void local_attn(const float* __restrict__ qkv, float* __restrict__ att) {
    const int tokenIdx = blockIdx.x;
    const int b = tokenIdx / NTOK;
    const int n = tokenIdx % NTOK;
    const int t  = n / (TOKEN_HH * TOKEN_WW);
    const int hy = (n / TOKEN_WW) % TOKEN_HH;
    const int wx = n % TOKEN_WW;
    const int head = threadIdx.x >> 5;
    const int lane = threadIdx.x & 31;

    const float* qptr = qkv + (size_t)tokenIdx * (3 * HID) + head * HDIM;
    const float q0 = qptr[lane];
    const float q1 = qptr[lane + 32];

    float s[27];
    int   nidx[27];
    bool  valid[27];

#pragma unroll
    for (int j = 0; j < 27; j++) {
        const int dt = j / 9 - 1;
        const int dh = (j / 3) % 3 - 1;
        const int dw = j % 3 - 1;
        const int tt = t + dt, hh = hy + dh, ww = wx + dw;
        const bool v = (tt >= 0) && (tt < TOKEN_T) &&
                       (hh >= 0) && (hh < TOKEN_HH) &&
                       (ww >= 0) && (ww < TOKEN_WW);
        valid[j] = v;
        const int nn = (tt * TOKEN_HH + hh) * TOKEN_WW + ww;
        nidx[j] = nn;
        float part = 0.0f;
        if (v) {
            const float* kptr = qkv + ((size_t)(b * NTOK + nn)) * (3 * HID) + HID + head * HDIM;
            part = q0 * kptr[lane] + q1 * kptr[lane + 32];
        }
#pragma unroll
        for (int off = 16; off; off >>= 1)
            part += __shfl_xor_sync(0xffffffffu, part, off);
        s[j] = v ? part * 0.125f : 0.0f;
    }

    float mx = s[0];
#pragma unroll
    for (int j = 1; j < 27; j++) mx = fmaxf(mx, s[j]);
    float denom = 0.0f;
#pragma unroll
    for (int j = 0; j < 27; j++) { s[j] = __expf(s[j] - mx); denom += s[j]; }
    const float inv = 1.0f / denom;

    float o0 = 0.0f, o1 = 0.0f;
#pragma unroll
    for (int j = 0; j < 27; j++) {
        if (valid[j]) {
            const float* vptr = qkv + ((size_t)(b * NTOK + nidx[j])) * (3 * HID) + 2 * HID + head * HDIM;
            const float w = s[j] * inv;
            o0 = fmaf(w, vptr[lane], o0);
            o1 = fmaf(w, vptr[lane + 32], o1);
        }
    }

    float* optr = att + (size_t)tokenIdx * HID + head * HDIM;
    optr[lane] = o0;
    optr[lane + 32] = o1;
}

// ---------------------------------------------------------------------------
// Launch
// ---------------------------------------------------------------------------
extern "C" void kernel_launch(void* const* d_in, const int* in_sizes, int n_in,
                              void* d_out, int out_size) {
    const float* x     = (const float*)d_in[0];  // (2, 2048, 1024)
    const float* w_qkv = (const float*)d_in[1];  // (3072, 1024)
    const float* w_out = (const float*)d_in[2];  // (1024, 1024)
    float* out = (float*)d_out;                  // (2, 2048, 1024)

    float *qkv, *att;
    __nv_bfloat16 *xhi, *xlo, *wqhi, *wqlo, *wohi, *wolo, *ahi, *alo;
    cudaGetSymbolAddress((void**)&qkv, g_qkv);
    cudaGetSymbolAddress((void**)&att, g_att);
    cudaGetSymbolAddress((void**)&xhi, g_xhi);
    cudaGetSymbolAddress((void**)&xlo, g_xlo);
    cudaGetSymbolAddress((void**)&wqhi, g_wqhi);
    cudaGetSymbolAddress((void**)&wqlo, g_wqlo);
    cudaGetSymbolAddress((void**)&wohi, g_wohi);
    cudaGetSymbolAddress((void**)&wolo, g_wolo);
    cudaGetSymbolAddress((void**)&ahi, g_ahi);
    cudaGetSymbolAddress((void**)&alo, g_alo);

    // split conversions
    {
        int n4 = M_TOT * HID / 4;
        cvt_split<<<(n4 + 255) / 256, 256>>>((const float4*)x, (uint2*)xhi, (uint2*)xlo, n4);
        n4 = 3 * HID * HID / 4;
        cvt_split<<<(n4 + 255) / 256, 256>>>((const float4*)w_qkv, (uint2*)wqhi, (uint2*)wqlo, n4);
        n4 = HID * HID / 4;
        cvt_split<<<(n4 + 255) / 256, 256>>>((const float4*)w_out, (uint2*)wohi, (uint2*)wolo, n4);
    }

    // 1) QKV: (4096,3072) = x * w_qkv^T
    {
        dim3 grid(3 * HID / 128, M_TOT / 128);
        gemm_bf16x3<<<grid, 256>>>(xhi, xlo, wqhi, wqlo, qkv, M_TOT, 3 * HID, HID);
    }

    // 2) Local attention
    local_attn<<<M_TOT, 512>>>(qkv, att);

    // 3) convert attention output, then out-proj: (4096,1024) = att * w_out^T
    {
        int n4 = M_TOT * HID / 4;
        cvt_split<<<(n4 + 255) / 256, 256>>>((const float4*)att, (uint2*)ahi, (uint2*)alo, n4);
        dim3 grid(HID / 128, M_TOT / 128);
        gemm_bf16x3<<<grid, 256>>>(ahi, alo, wohi, wolo, out, M_TOT, HID, HID);
    }
}

// round 4
// speedup vs baseline: 2.4534x; 1.3121x over previous
#include <cuda_runtime.h>
#include <cuda_bf16.h>
#include <cstdint>

// ---------------------------------------------------------------------------
// LocalAttention: x(2,2048,1024) -> qkv gemm -> 27-neighbor local attention
//                 (8x16x16 grid, 16 heads x 64 dim) -> out-proj gemm.
// Round 4: mma.sync bf16 hi/lo 3-product GEMM with cp.async 2-stage pipeline
//          + smem-tiled attention (per head, 4x4x4 token tile, 6^3 halo).
// (tcgen05 unavailable: harness PTX target is sm_100 virtual arch.)
// ---------------------------------------------------------------------------

#define TOKEN_T  8
#define TOKEN_HH 16
#define TOKEN_WW 16
#define NTOK     2048
#define BATCH    2
#define HID      1024
#define NHEAD    16
#define HDIM     64
#define M_TOT    (BATCH * NTOK)   // 4096

// Scratch (device globals: allocation-free per harness rules)
__device__ float g_qkv[(size_t)M_TOT * 3 * HID];
__device__ float g_att[(size_t)M_TOT * HID];

__device__ __nv_bfloat16 g_xhi[(size_t)M_TOT * HID];
__device__ __nv_bfloat16 g_xlo[(size_t)M_TOT * HID];
__device__ __nv_bfloat16 g_wqhi[(size_t)3 * HID * HID];
__device__ __nv_bfloat16 g_wqlo[(size_t)3 * HID * HID];
__device__ __nv_bfloat16 g_wohi[(size_t)HID * HID];
__device__ __nv_bfloat16 g_wolo[(size_t)HID * HID];
__device__ __nv_bfloat16 g_ahi[(size_t)M_TOT * HID];
__device__ __nv_bfloat16 g_alo[(size_t)M_TOT * HID];

// ---------------------------------------------------------------------------
// fp32 -> (bf16 hi, bf16 lo) split.  lo = bf16(v - float(hi)).
// ---------------------------------------------------------------------------
__global__ void cvt_split(const float4* __restrict__ in,
                          uint2* __restrict__ hi, uint2* __restrict__ lo,
                          int n4) {
    int i = blockIdx.x * blockDim.x + threadIdx.x;
    if (i >= n4) return;
    float4 v = in[i];
    __nv_bfloat16 h0 = __float2bfloat16(v.x);
    __nv_bfloat16 h1 = __float2bfloat16(v.y);
    __nv_bfloat16 h2 = __float2bfloat16(v.z);
    __nv_bfloat16 h3 = __float2bfloat16(v.w);
    __nv_bfloat16 l0 = __float2bfloat16(v.x - __bfloat162float(h0));
    __nv_bfloat16 l1 = __float2bfloat16(v.y - __bfloat162float(h1));
    __nv_bfloat16 l2 = __float2bfloat16(v.z - __bfloat162float(h2));
    __nv_bfloat16 l3 = __float2bfloat16(v.w - __bfloat162float(h3));
    __nv_bfloat162 ha = __nv_bfloat162(h0, h1), hb = __nv_bfloat162(h2, h3);
    __nv_bfloat162 la = __nv_bfloat162(l0, l1), lb = __nv_bfloat162(l2, l3);
    uint2 H, L;
    H.x = *reinterpret_cast<uint32_t*>(&ha);
    H.y = *reinterpret_cast<uint32_t*>(&hb);
    L.x = *reinterpret_cast<uint32_t*>(&la);
    L.y = *reinterpret_cast<uint32_t*>(&lb);
    hi[i] = H;
    lo[i] = L;
}

// ---------------------------------------------------------------------------
// mma.sync helpers
// ---------------------------------------------------------------------------
__device__ __forceinline__ void ldsm4(uint32_t* r, uint32_t addr) {
    asm volatile("ldmatrix.sync.aligned.m8n8.x4.shared.b16 {%0,%1,%2,%3},[%4];\n"
                 : "=r"(r[0]), "=r"(r[1]), "=r"(r[2]), "=r"(r[3]) : "r"(addr));
}
__device__ __forceinline__ void ldsm2(uint32_t* r, uint32_t addr) {
    asm volatile("ldmatrix.sync.aligned.m8n8.x2.shared.b16 {%0,%1},[%2];\n"
                 : "=r"(r[0]), "=r"(r[1]) : "r"(addr));
}
__device__ __forceinline__ void mma16816(float* d, const uint32_t* a, const uint32_t* b) {
    asm volatile("mma.sync.aligned.m16n8k16.row.col.f32.bf16.bf16.f32 "
                 "{%0,%1,%2,%3},{%4,%5,%6,%7},{%8,%9},{%0,%1,%2,%3};\n"
                 : "+f"(d[0]), "+f"(d[1]), "+f"(d[2]), "+f"(d[3])
                 : "r"(a[0]), "r"(a[1]), "r"(a[2]), "r"(a[3]),
                   "r"(b[0]), "r"(b[1]));
}
__device__ __forceinline__ void cp_async8(uint32_t saddr, const void* gaddr) {
    asm volatile("cp.async.ca.shared.global [%0], [%1], 8;\n"
                 :: "r"(saddr), "l"(gaddr) : "memory");
}

// smem layout (per stage): Ahi | Alo | Bhi | Blo, each 128 rows x 40 halves
#define GKP        40                    // padded row stride (halves)
#define GROW_B     (GKP * 2)             // 80 bytes per row
#define GMAT_B     (128 * GROW_B)        // 10240 B per matrix
#define GSTAGE_B   (4 * GMAT_B)          // 40960 B per stage
#define GSMEM_B    (2 * GSTAGE_B)        // 81920 B total

// ---------------------------------------------------------------------------
// Pipelined tensor-core GEMM (NT): C = Ahi*Bhi^T + Ahi*Blo^T + Alo*Bhi^T
// A[M,K], B[N,K] K-contiguous bf16. Tile 128x128, BK=32, 2-stage cp.async.
// ---------------------------------------------------------------------------
__global__ __launch_bounds__(256, 2)
void gemm_bf16x3_pipe(const __nv_bfloat16* __restrict__ Ahi,
                      const __nv_bfloat16* __restrict__ Alo,
                      const __nv_bfloat16* __restrict__ Bhi,
                      const __nv_bfloat16* __restrict__ Blo,
                      float* __restrict__ C, int M, int N, int K) {
    extern __shared__ __align__(16) char smem_raw[];
    const uint32_t sb = (uint32_t)__cvta_generic_to_shared(smem_raw);

    const int tid  = threadIdx.x;
    const int lane = tid & 31;
    const int warp = tid >> 5;
    const int wm = (warp >> 2) * 64;
    const int wn = (warp & 3) * 32;
    const int mrow0 = blockIdx.y * 128;
    const int ncol0 = blockIdx.x * 128;

    float acc[4][4][4];
#pragma unroll
    for (int mi = 0; mi < 4; mi++)
#pragma unroll
        for (int ni = 0; ni < 4; ni++)
#pragma unroll
            for (int r = 0; r < 4; r++) acc[mi][ni][r] = 0.0f;

    const __nv_bfloat16* pAh = Ahi + (size_t)mrow0 * K;
    const __nv_bfloat16* pAl = Alo + (size_t)mrow0 * K;
    const __nv_bfloat16* pBh = Bhi + (size_t)ncol0 * K;
    const __nv_bfloat16* pBl = Blo + (size_t)ncol0 * K;

    // cp.async loader: 1024 chunks of 8B (4 halves) per matrix per stage
    auto load_stage = [&](int buf, int k0) {
        const uint32_t stage = sb + buf * GSTAGE_B;
#pragma unroll
        for (int it = 0; it < 4; it++) {
            const int id  = it * 256 + tid;      // 0..1023
            const int row = id >> 3;             // 0..127
            const int c   = id & 7;              // 8B chunk 0..7
            const uint32_t soff = (uint32_t)(row * GROW_B + c * 8);
            const size_t goff = (size_t)row * K + k0 + c * 4;
            cp_async8(stage + 0 * GMAT_B + soff, pAh + goff);
            cp_async8(stage + 1 * GMAT_B + soff, pAl + goff);
            cp_async8(stage + 2 * GMAT_B + soff, pBh + goff);
            cp_async8(stage + 3 * GMAT_B + soff, pBl + goff);
        }
        asm volatile("cp.async.commit_group;\n" ::: "memory");
    };

    // ldmatrix lane geometry (round-2 proven layout, stride 40 halves)
    const int a_row = (lane & 15);
    const int a_kof = (lane >> 4) << 3;
    const int b_row = (lane & 7);
    const int b_kof = (lane & 8);

    const int nchunk = K / 32;
    load_stage(0, 0);

    for (int c = 0; c < nchunk; c++) {
        const int cur = c & 1;
        if (c + 1 < nchunk) {
            load_stage(cur ^ 1, (c + 1) * 32);
            asm volatile("cp.async.wait_group 1;\n" ::: "memory");
        } else {
            asm volatile("cp.async.wait_group 0;\n" ::: "memory");
        }
        __syncthreads();

        const uint32_t stage = sb + cur * GSTAGE_B;
        const uint32_t Ah = stage + 0 * GMAT_B;
        const uint32_t Al = stage + 1 * GMAT_B;
        const uint32_t Bh = stage + 2 * GMAT_B;
        const uint32_t Bl = stage + 3 * GMAT_B;

#pragma unroll
        for (int kk = 0; kk < 32; kk += 16) {
            uint32_t a[4][4];
            uint32_t bh[4][2], bl[4][2];
#pragma unroll
            for (int mi = 0; mi < 4; mi++)
                ldsm4(a[mi], Ah + (uint32_t)((wm + mi * 16 + a_row) * GROW_B + (kk + a_kof) * 2));
#pragma unroll
            for (int ni = 0; ni < 4; ni++) {
                ldsm2(bh[ni], Bh + (uint32_t)((wn + ni * 8 + b_row) * GROW_B + (kk + b_kof) * 2));
                ldsm2(bl[ni], Bl + (uint32_t)((wn + ni * 8 + b_row) * GROW_B + (kk + b_kof) * 2));
            }
#pragma unroll
            for (int mi = 0; mi < 4; mi++)
#pragma unroll
                for (int ni = 0; ni < 4; ni++) {
                    mma16816(acc[mi][ni], a[mi], bh[ni]);
                    mma16816(acc[mi][ni], a[mi], bl[ni]);
                }
#pragma unroll
            for (int mi = 0; mi < 4; mi++)
                ldsm4(a[mi], Al + (uint32_t)((wm + mi * 16 + a_row) * GROW_B + (kk + a_kof) * 2));
#pragma unroll
            for (int mi = 0; mi < 4; mi++)
#pragma unroll
                for (int ni = 0; ni < 4; ni++)
                    mma16816(acc[mi][ni], a[mi], bh[ni]);
        }
        __syncthreads();
    }

    const int em = mrow0 + wm + (lane >> 2);
    const int en = ncol0 + wn + (lane & 3) * 2;
#pragma unroll
    for (int mi = 0; mi < 4; mi++) {
#pragma unroll
        for (int ni = 0; ni < 4; ni++) {
            float* c0 = C + (size_t)(em + mi * 16) * N + en + ni * 8;
            float* c1 = C + (size_t)(em + mi * 16 + 8) * N + en + ni * 8;
            *reinterpret_cast<float2*>(c0) = make_float2(acc[mi][ni][0], acc[mi][ni][1]);
            *reinterpret_cast<float2*>(c1) = make_float2(acc[mi][ni][2], acc[mi][ni][3]);
        }
    }
}

// ---------------------------------------------------------------------------
// Smem-tiled local attention.
// Block = (4x4x4 token tile) x 1 head x 1 batch; 6x6x6 halo of k,v (64-dim
// head slice, fp32) in smem. OOB halo rows are zero -> logit exactly 0 and
// value 0, matching the reference's zero-padding.
// ---------------------------------------------------------------------------
#define AT_HALO 216
#define KSTR    66        // floats per halo row (64 + 2 pad, 8B-aligned rows)
#define AT_SMEM ((2 * AT_HALO * KSTR + 64 * 64) * 4)

__global__ __launch_bounds__(256, 1)
void local_attn_tiled(const float* __restrict__ qkv, float* __restrict__ att) {
    extern __shared__ __align__(16) float sm[];
    float* k_s = sm;
    float* v_s = sm + AT_HALO * KSTR;
    float* q_s = v_s + AT_HALO * KSTR;

    const int tile = blockIdx.x;          // 0..31
    const int head = blockIdx.y;
    const int b    = blockIdx.z;
    const int t0 = (tile >> 4) * 4;
    const int h0 = ((tile >> 2) & 3) * 4;
    const int w0 = (tile & 3) * 4;
    const int tid = threadIdx.x;

    // halo load: 216 tokens x 32 float2 each for k and v
    for (int idx = tid; idx < AT_HALO * 32; idx += 256) {
        const int tok = idx >> 5;
        const int f2  = idx & 31;
        const int ht = tok / 36, hh = (tok / 6) % 6, hw = tok % 6;
        const int gt = t0 - 1 + ht, gh = h0 - 1 + hh, gw = w0 - 1 + hw;
        float2 kv = make_float2(0.f, 0.f), vv = make_float2(0.f, 0.f);
        if (gt >= 0 && gt < TOKEN_T && gh >= 0 && gh < TOKEN_HH &&
            gw >= 0 && gw < TOKEN_WW) {
            const int n = (gt * TOKEN_HH + gh) * TOKEN_WW + gw;
            const float* base = qkv + ((size_t)(b * NTOK + n)) * (3 * HID) + head * HDIM + f2 * 2;
            kv = *reinterpret_cast<const float2*>(base + HID);
            vv = *reinterpret_cast<const float2*>(base + 2 * HID);
        }
        *reinterpret_cast<float2*>(&k_s[tok * KSTR + f2 * 2]) = kv;
        *reinterpret_cast<float2*>(&v_s[tok * KSTR + f2 * 2]) = vv;
    }
    // q load: 64 tokens x 16 float4
    for (int idx = tid; idx < 64 * 16; idx += 256) {
        const int tok = idx >> 4, f4 = idx & 15;
        const int lt = tok >> 4, lh = (tok >> 2) & 3, lw = tok & 3;
        const int n = ((t0 + lt) * TOKEN_HH + (h0 + lh)) * TOKEN_WW + (w0 + lw);
        float4 qv = *reinterpret_cast<const float4*>(
            qkv + ((size_t)(b * NTOK + n)) * (3 * HID) + head * HDIM + f4 * 4);
        *reinterpret_cast<float4*>(&q_s[tok * 64 + f4 * 4]) = qv;
    }
    __syncthreads();

    const int warp = tid >> 5, lane = tid & 31;
#pragma unroll
    for (int i = 0; i < 8; i++) {
        const int tok = warp * 8 + i;
        const int lt = tok >> 4, lh = (tok >> 2) & 3, lw = tok & 3;

        // lanes 0..26: each computes one neighbor's full 64-dim logit
        float s = 0.f;
        int hrow = 0;
        if (lane < 27) {
            const int dt = lane / 9, dh = (lane / 3) % 3, dw = lane % 3;
            hrow = ((lt + dt) * 6 + (lh + dh)) * 6 + (lw + dw);
            const float2* kp = reinterpret_cast<const float2*>(&k_s[hrow * KSTR]);
            const float2* qp = reinterpret_cast<const float2*>(&q_s[tok * 64]);
#pragma unroll
            for (int d = 0; d < 32; d++) {
                const float2 kk2 = kp[d];
                const float2 qq2 = qp[d];
                s = fmaf(qq2.x, kk2.x, s);
                s = fmaf(qq2.y, kk2.y, s);
            }
            s *= 0.125f;   // 64^-0.5
        }
        float sl = (lane < 27) ? s : -1e30f;
#pragma unroll
        for (int off = 16; off; off >>= 1)
            sl = fmaxf(sl, __shfl_xor_sync(0xffffffffu, sl, off));
        const float e = (lane < 27) ? __expf(s - sl) : 0.f;
        float den = e;
#pragma unroll
        for (int off = 16; off; off >>= 1)
            den += __shfl_xor_sync(0xffffffffu, den, off);
        const float w = e / den;

        // value accumulation: lane owns dims {lane, lane+32}
        float o0 = 0.f, o1 = 0.f;
#pragma unroll
        for (int j = 0; j < 27; j++) {
            const float wj = __shfl_sync(0xffffffffu, w, j);
            const int   rj = __shfl_sync(0xffffffffu, hrow, j);
            o0 = fmaf(wj, v_s[rj * KSTR + lane], o0);
            o1 = fmaf(wj, v_s[rj * KSTR + lane + 32], o1);
        }
        const int n = ((t0 + lt) * TOKEN_HH + (h0 + lh)) * TOKEN_WW + (w0 + lw);
        float* op = att + ((size_t)(b * NTOK + n)) * HID + head * HDIM;
        op[lane] = o0;
        op[lane + 32] = o1;
    }
}

// ---------------------------------------------------------------------------
// Launch
// ---------------------------------------------------------------------------
extern "C" void kernel_launch(void* const* d_in, const int* in_sizes, int n_in,
                              void* d_out, int out_size) {
    const float* x     = (const float*)d_in[0];
    const float* w_qkv = (const float*)d_in[1];
    const float* w_out = (const float*)d_in[2];
    float* out = (float*)d_out;

    float *qkv, *att;
    __nv_bfloat16 *xhi, *xlo, *wqhi, *wqlo, *wohi, *wolo, *ahi, *alo;
    cudaGetSymbolAddress((void**)&qkv, g_qkv);
    cudaGetSymbolAddress((void**)&att, g_att);
    cudaGetSymbolAddress((void**)&xhi, g_xhi);
    cudaGetSymbolAddress((void**)&xlo, g_xlo);
    cudaGetSymbolAddress((void**)&wqhi, g_wqhi);
    cudaGetSymbolAddress((void**)&wqlo, g_wqlo);
    cudaGetSymbolAddress((void**)&wohi, g_wohi);
    cudaGetSymbolAddress((void**)&wolo, g_wolo);
    cudaGetSymbolAddress((void**)&ahi, g_ahi);
    cudaGetSymbolAddress((void**)&alo, g_alo);

    cudaFuncSetAttribute(gemm_bf16x3_pipe,
                         cudaFuncAttributeMaxDynamicSharedMemorySize, GSMEM_B);
    cudaFuncSetAttribute(local_attn_tiled,
                         cudaFuncAttributeMaxDynamicSharedMemorySize, AT_SMEM);

    // split conversions
    {
        int n4 = M_TOT * HID / 4;
        cvt_split<<<(n4 + 255) / 256, 256>>>((const float4*)x, (uint2*)xhi, (uint2*)xlo, n4);
        n4 = 3 * HID * HID / 4;
        cvt_split<<<(n4 + 255) / 256, 256>>>((const float4*)w_qkv, (uint2*)wqhi, (uint2*)wqlo, n4);
        n4 = HID * HID / 4;
        cvt_split<<<(n4 + 255) / 256, 256>>>((const float4*)w_out, (uint2*)wohi, (uint2*)wolo, n4);
    }

    // 1) QKV: (4096,3072) = x * w_qkv^T
    {
        dim3 grid(3 * HID / 128, M_TOT / 128);
        gemm_bf16x3_pipe<<<grid, 256, GSMEM_B>>>(xhi, xlo, wqhi, wqlo, qkv,
                                                 M_TOT, 3 * HID, HID);
    }

    // 2) local attention (tiled)
    {
        dim3 grid(32, NHEAD, BATCH);
        local_attn_tiled<<<grid, 256, AT_SMEM>>>(qkv, att);
    }

    // 3) out-proj
    {
        int n4 = M_TOT * HID / 4;
        cvt_split<<<(n4 + 255) / 256, 256>>>((const float4*)att, (uint2*)ahi, (uint2*)alo, n4);
        dim3 grid(HID / 128, M_TOT / 128);
        gemm_bf16x3_pipe<<<grid, 256, GSMEM_B>>>(ahi, alo, wohi, wolo, out,
                                                 M_TOT, HID, HID);
    }
}

// round 5
// speedup vs baseline: 4.1042x; 1.6729x over previous
#include <cuda_runtime.h>
#include <cuda_fp16.h>
#include <cstdint>

// ---------------------------------------------------------------------------
// LocalAttention: x(2,2048,1024) -> qkv gemm -> 27-neighbor local attention
//                 (8x16x16 grid, 16 heads x 64 dim) -> out-proj gemm.
// Round 5: single-pass fp16 tensor-core GEMMs (error model: ~5e-4 rel, vs
//          1e-3 budget; inputs are fixed-seed so rel_err is deterministic),
//          3-stage cp.async pipeline, ldsm4-merged B fragments,
//          attention writes fp16 directly (fused out-proj operand).
// ---------------------------------------------------------------------------

#define TOKEN_T  8
#define TOKEN_HH 16
#define TOKEN_WW 16
#define NTOK     2048
#define BATCH    2
#define HID      1024
#define NHEAD    16
#define HDIM     64
#define M_TOT    (BATCH * NTOK)   // 4096

// Scratch (device globals: allocation-free per harness rules)
__device__ float  g_qkv[(size_t)M_TOT * 3 * HID];          // fp32 qkv
__device__ __half g_xh[(size_t)M_TOT * HID];               // fp16 x
__device__ __half g_wqh[(size_t)3 * HID * HID];            // fp16 w_qkv
__device__ __half g_woh[(size_t)HID * HID];                // fp16 w_out
__device__ __half g_atth[(size_t)M_TOT * HID];             // fp16 attention out

// ---------------------------------------------------------------------------
// Fused fp32 -> fp16 conversion of x, w_qkv, w_out in one launch.
// ---------------------------------------------------------------------------
#define X4  (M_TOT * HID / 4)          // 1048576
#define WQ4 (3 * HID * HID / 4)        // 786432
#define WO4 (HID * HID / 4)            // 262144

__global__ void cvt_all(const float4* __restrict__ x,
                        const float4* __restrict__ wq,
                        const float4* __restrict__ wo,
                        uint2* __restrict__ xh,
                        uint2* __restrict__ wqh,
                        uint2* __restrict__ woh) {
    int i = blockIdx.x * blockDim.x + threadIdx.x;
    const float4* src;
    uint2* dst;
    int j;
    if (i < X4)                { src = x;  dst = xh;  j = i; }
    else if (i < X4 + WQ4)     { src = wq; dst = wqh; j = i - X4; }
    else if (i < X4 + WQ4 + WO4) { src = wo; dst = woh; j = i - X4 - WQ4; }
    else return;
    float4 v = src[j];
    __half2 a = __floats2half2_rn(v.x, v.y);
    __half2 b = __floats2half2_rn(v.z, v.w);
    uint2 o;
    o.x = *reinterpret_cast<uint32_t*>(&a);
    o.y = *reinterpret_cast<uint32_t*>(&b);
    dst[j] = o;
}

// ---------------------------------------------------------------------------
// mma.sync helpers
// ---------------------------------------------------------------------------
__device__ __forceinline__ void ldsm4(uint32_t* r, uint32_t addr) {
    asm volatile("ldmatrix.sync.aligned.m8n8.x4.shared.b16 {%0,%1,%2,%3},[%4];\n"
                 : "=r"(r[0]), "=r"(r[1]), "=r"(r[2]), "=r"(r[3]) : "r"(addr));
}
__device__ __forceinline__ void mma16816(float* d, const uint32_t* a, const uint32_t* b) {
    asm volatile("mma.sync.aligned.m16n8k16.row.col.f32.f16.f16.f32 "
                 "{%0,%1,%2,%3},{%4,%5,%6,%7},{%8,%9},{%0,%1,%2,%3};\n"
                 : "+f"(d[0]), "+f"(d[1]), "+f"(d[2]), "+f"(d[3])
                 : "r"(a[0]), "r"(a[1]), "r"(a[2]), "r"(a[3]),
                   "r"(b[0]), "r"(b[1]));
}
__device__ __forceinline__ void cp_async8(uint32_t saddr, const void* gaddr) {
    asm volatile("cp.async.ca.shared.global [%0], [%1], 8;\n"
                 :: "r"(saddr), "l"(gaddr) : "memory");
}

// smem per stage: A | B, each 128 rows x 40 halves (80 B rows, conflict-free)
#define GKP      40
#define GROW_B   (GKP * 2)              // 80 B per row
#define GMAT_B   (128 * GROW_B)         // 10240 B
#define GSTAGE_B (2 * GMAT_B)           // 20480 B
#define GSTAGES  3
#define GSMEM_B  (GSTAGES * GSTAGE_B)   // 61440 B

// ---------------------------------------------------------------------------
// fp16 tensor-core GEMM (NT): C[M,N] = A[M,K] * B[N,K]^T, fp32 accumulate.
// Tile 128x128, BK=32, 3-stage cp.async pipeline, 8 warps (64x32 warp tile).
// ---------------------------------------------------------------------------
__global__ __launch_bounds__(256, 2)
void gemm_f16_pipe(const __half* __restrict__ A, const __half* __restrict__ B,
                   float* __restrict__ C, int M, int N, int K) {
    extern __shared__ __align__(16) char smem_raw[];
    const uint32_t sb = (uint32_t)__cvta_generic_to_shared(smem_raw);

    const int tid  = threadIdx.x;
    const int lane = tid & 31;
    const int warp = tid >> 5;
    const int wm = (warp >> 2) * 64;
    const int wn = (warp & 3) * 32;
    const int mrow0 = blockIdx.y * 128;
    const int ncol0 = blockIdx.x * 128;

    float acc[4][4][4];
#pragma unroll
    for (int mi = 0; mi < 4; mi++)
#pragma unroll
        for (int ni = 0; ni < 4; ni++)
#pragma unroll
            for (int r = 0; r < 4; r++) acc[mi][ni][r] = 0.0f;

    const __half* pA = A + (size_t)mrow0 * K;
    const __half* pB = B + (size_t)ncol0 * K;

    // loader: per stage, per matrix: 1024 chunks of 8B; each thread does 4 A + 4 B
    auto load_stage = [&](int buf, int k0) {
        const uint32_t stage = sb + buf * GSTAGE_B;
#pragma unroll
        for (int it = 0; it < 4; it++) {
            const int id  = it * 256 + tid;     // 0..1023
            const int row = id >> 3;
            const int c   = id & 7;
            const uint32_t soff = (uint32_t)(row * GROW_B + c * 8);
            const size_t goff = (size_t)row * K + k0 + c * 4;
            cp_async8(stage + soff, pA + goff);
            cp_async8(stage + GMAT_B + soff, pB + goff);
        }
        asm volatile("cp.async.commit_group;\n" ::: "memory");
    };

    // ldmatrix lane geometry
    const int a_row = (lane & 15);
    const int a_kof = (lane >> 4) << 3;
    // B x4: covers 2 n-tiles (16 rows) + both k-halves
    const int b_loc = ((lane >> 3) & 1) * 8 + (lane & 7);   // row within 16
    const int b_kof = (lane >> 4) << 3;

    const int nchunk = K / 32;
    load_stage(0, 0);
    load_stage(1, 32);

    for (int c = 0; c < nchunk; c++) {
        if (c + 2 < nchunk) {
            load_stage((c + 2) % GSTAGES, (c + 2) * 32);
            asm volatile("cp.async.wait_group 2;\n" ::: "memory");
        } else if (c + 1 < nchunk) {
            asm volatile("cp.async.wait_group 1;\n" ::: "memory");
        } else {
            asm volatile("cp.async.wait_group 0;\n" ::: "memory");
        }
        __syncthreads();

        const uint32_t stage = sb + (c % GSTAGES) * GSTAGE_B;
        const uint32_t As = stage;
        const uint32_t Bs = stage + GMAT_B;

#pragma unroll
        for (int kk = 0; kk < 32; kk += 16) {
            uint32_t a[4][4];
            uint32_t b[4][2];
#pragma unroll
            for (int mi = 0; mi < 4; mi++)
                ldsm4(a[mi], As + (uint32_t)((wm + mi * 16 + a_row) * GROW_B + (kk + a_kof) * 2));
#pragma unroll
            for (int p = 0; p < 2; p++) {
                uint32_t r[4];
                ldsm4(r, Bs + (uint32_t)((wn + p * 16 + b_loc) * GROW_B + (kk + b_kof) * 2));
                b[p * 2 + 0][0] = r[0]; b[p * 2 + 0][1] = r[2];
                b[p * 2 + 1][0] = r[1]; b[p * 2 + 1][1] = r[3];
            }
#pragma unroll
            for (int mi = 0; mi < 4; mi++)
#pragma unroll
                for (int ni = 0; ni < 4; ni++)
                    mma16816(acc[mi][ni], a[mi], b[ni]);
        }
        __syncthreads();
    }

    const int em = mrow0 + wm + (lane >> 2);
    const int en = ncol0 + wn + (lane & 3) * 2;
#pragma unroll
    for (int mi = 0; mi < 4; mi++) {
#pragma unroll
        for (int ni = 0; ni < 4; ni++) {
            float* c0 = C + (size_t)(em + mi * 16) * N + en + ni * 8;
            float* c1 = C + (size_t)(em + mi * 16 + 8) * N + en + ni * 8;
            *reinterpret_cast<float2*>(c0) = make_float2(acc[mi][ni][0], acc[mi][ni][1]);
            *reinterpret_cast<float2*>(c1) = make_float2(acc[mi][ni][2], acc[mi][ni][3]);
        }
    }
}

// ---------------------------------------------------------------------------
// Smem-tiled local attention; writes fp16 output directly (out-proj operand).
// Block = (4x4x4 token tile) x head x batch; 6x6x6 fp32 halo of k,v in smem.
// OOB halo rows are zero -> logit exactly 0 in softmax + value 0, matching
// the reference's zero-padding.
// ---------------------------------------------------------------------------
#define AT_HALO 216
#define KSTR    66
#define AT_SMEM ((2 * AT_HALO * KSTR + 64 * 64) * 4)

__global__ __launch_bounds__(256, 1)
void local_attn_tiled(const float* __restrict__ qkv, __half* __restrict__ att) {
    extern __shared__ __align__(16) float sm[];
    float* k_s = sm;
    float* v_s = sm + AT_HALO * KSTR;
    float* q_s = v_s + AT_HALO * KSTR;

    const int tile = blockIdx.x;
    const int head = blockIdx.y;
    const int b    = blockIdx.z;
    const int t0 = (tile >> 4) * 4;
    const int h0 = ((tile >> 2) & 3) * 4;
    const int w0 = (tile & 3) * 4;
    const int tid = threadIdx.x;

    for (int idx = tid; idx < AT_HALO * 32; idx += 256) {
        const int tok = idx >> 5;
        const int f2  = idx & 31;
        const int ht = tok / 36, hh = (tok / 6) % 6, hw = tok % 6;
        const int gt = t0 - 1 + ht, gh = h0 - 1 + hh, gw = w0 - 1 + hw;
        float2 kv = make_float2(0.f, 0.f), vv = make_float2(0.f, 0.f);
        if (gt >= 0 && gt < TOKEN_T && gh >= 0 && gh < TOKEN_HH &&
            gw >= 0 && gw < TOKEN_WW) {
            const int n = (gt * TOKEN_HH + gh) * TOKEN_WW + gw;
            const float* base = qkv + ((size_t)(b * NTOK + n)) * (3 * HID) + head * HDIM + f2 * 2;
            kv = *reinterpret_cast<const float2*>(base + HID);
            vv = *reinterpret_cast<const float2*>(base + 2 * HID);
        }
        *reinterpret_cast<float2*>(&k_s[tok * KSTR + f2 * 2]) = kv;
        *reinterpret_cast<float2*>(&v_s[tok * KSTR + f2 * 2]) = vv;
    }
    for (int idx = tid; idx < 64 * 16; idx += 256) {
        const int tok = idx >> 4, f4 = idx & 15;
        const int lt = tok >> 4, lh = (tok >> 2) & 3, lw = tok & 3;
        const int n = ((t0 + lt) * TOKEN_HH + (h0 + lh)) * TOKEN_WW + (w0 + lw);
        float4 qv = *reinterpret_cast<const float4*>(
            qkv + ((size_t)(b * NTOK + n)) * (3 * HID) + head * HDIM + f4 * 4);
        *reinterpret_cast<float4*>(&q_s[tok * 64 + f4 * 4]) = qv;
    }
    __syncthreads();

    const int warp = tid >> 5, lane = tid & 31;
#pragma unroll
    for (int i = 0; i < 8; i++) {
        const int tok = warp * 8 + i;
        const int lt = tok >> 4, lh = (tok >> 2) & 3, lw = tok & 3;

        float s = 0.f;
        int hrow = 0;
        if (lane < 27) {
            const int dt = lane / 9, dh = (lane / 3) % 3, dw = lane % 3;
            hrow = ((lt + dt) * 6 + (lh + dh)) * 6 + (lw + dw);
            const float2* kp = reinterpret_cast<const float2*>(&k_s[hrow * KSTR]);
            const float2* qp = reinterpret_cast<const float2*>(&q_s[tok * 64]);
#pragma unroll
            for (int d = 0; d < 32; d++) {
                const float2 kk2 = kp[d];
                const float2 qq2 = qp[d];
                s = fmaf(qq2.x, kk2.x, s);
                s = fmaf(qq2.y, kk2.y, s);
            }
            s *= 0.125f;
        }
        float sl = (lane < 27) ? s : -1e30f;
#pragma unroll
        for (int off = 16; off; off >>= 1)
            sl = fmaxf(sl, __shfl_xor_sync(0xffffffffu, sl, off));
        const float e = (lane < 27) ? __expf(s - sl) : 0.f;
        float den = e;
#pragma unroll
        for (int off = 16; off; off >>= 1)
            den += __shfl_xor_sync(0xffffffffu, den, off);
        const float w = e / den;

        float o0 = 0.f, o1 = 0.f;
#pragma unroll
        for (int j = 0; j < 27; j++) {
            const float wj = __shfl_sync(0xffffffffu, w, j);
            const int   rj = __shfl_sync(0xffffffffu, hrow, j);
            o0 = fmaf(wj, v_s[rj * KSTR + lane], o0);
            o1 = fmaf(wj, v_s[rj * KSTR + lane + 32], o1);
        }
        const int n = ((t0 + lt) * TOKEN_HH + (h0 + lh)) * TOKEN_WW + (w0 + lw);
        __half* op = att + ((size_t)(b * NTOK + n)) * HID + head * HDIM;
        op[lane]      = __float2half_rn(o0);
        op[lane + 32] = __float2half_rn(o1);
    }
}

// ---------------------------------------------------------------------------
// Launch
// ---------------------------------------------------------------------------
extern "C" void kernel_launch(void* const* d_in, const int* in_sizes, int n_in,
                              void* d_out, int out_size) {
    const float* x     = (const float*)d_in[0];
    const float* w_qkv = (const float*)d_in[1];
    const float* w_out = (const float*)d_in[2];
    float* out = (float*)d_out;

    float* qkv;
    __half *xh, *wqh, *woh, *atth;
    cudaGetSymbolAddress((void**)&qkv, g_qkv);
    cudaGetSymbolAddress((void**)&xh, g_xh);
    cudaGetSymbolAddress((void**)&wqh, g_wqh);
    cudaGetSymbolAddress((void**)&woh, g_woh);
    cudaGetSymbolAddress((void**)&atth, g_atth);

    cudaFuncSetAttribute(gemm_f16_pipe,
                         cudaFuncAttributeMaxDynamicSharedMemorySize, GSMEM_B);
    cudaFuncSetAttribute(local_attn_tiled,
                         cudaFuncAttributeMaxDynamicSharedMemorySize, AT_SMEM);

    // 0) fused conversions (x, w_qkv, w_out -> fp16)
    {
        const int total = X4 + WQ4 + WO4;
        cvt_all<<<(total + 255) / 256, 256>>>((const float4*)x, (const float4*)w_qkv,
                                              (const float4*)w_out,
                                              (uint2*)xh, (uint2*)wqh, (uint2*)woh);
    }

    // 1) QKV: (4096,3072) = x * w_qkv^T  (fp32 out for attention accuracy)
    {
        dim3 grid(3 * HID / 128, M_TOT / 128);
        gemm_f16_pipe<<<grid, 256, GSMEM_B>>>(xh, wqh, qkv, M_TOT, 3 * HID, HID);
    }

    // 2) local attention (writes fp16 att directly)
    {
        dim3 grid(32, NHEAD, BATCH);
        local_attn_tiled<<<grid, 256, AT_SMEM>>>(qkv, atth);
    }

    // 3) out-proj: (4096,1024) = att * w_out^T
    {
        dim3 grid(HID / 128, M_TOT / 128);
        gemm_f16_pipe<<<grid, 256, GSMEM_B>>>(atth, woh, out, M_TOT, HID, HID);
    }
}

// round 6
// speedup vs baseline: 4.9147x; 1.1975x over previous
#include <cuda_runtime.h>
#include <cuda_fp16.h>
#include <cstdint>
#include <type_traits>

// ---------------------------------------------------------------------------
// LocalAttention: x(2,2048,1024) -> qkv gemm -> 27-neighbor local attention
//                 (8x16x16 grid, 16 heads x 64 dim) -> out-proj gemm.
// Round 6: fp16 end-to-end pipeline (fp32 accumulate everywhere):
//   - 4-stage cp.async GEMM, single __syncthreads per chunk, hoisted ldsm addrs
//   - QKV GEMM writes fp16; attention consumes/produces fp16 (fp32 math)
// ---------------------------------------------------------------------------

#define TOKEN_T  8
#define TOKEN_HH 16
#define TOKEN_WW 16
#define NTOK     2048
#define BATCH    2
#define HID      1024
#define NHEAD    16
#define HDIM     64
#define M_TOT    (BATCH * NTOK)   // 4096

// Scratch (device globals: allocation-free per harness rules)
__device__ __half g_qkvh[(size_t)M_TOT * 3 * HID];   // fp16 qkv
__device__ __half g_xh[(size_t)M_TOT * HID];
__device__ __half g_wqh[(size_t)3 * HID * HID];
__device__ __half g_woh[(size_t)HID * HID];
__device__ __half g_atth[(size_t)M_TOT * HID];

// ---------------------------------------------------------------------------
// Fused fp32 -> fp16 conversion of x, w_qkv, w_out in one launch.
// ---------------------------------------------------------------------------
#define X4  (M_TOT * HID / 4)
#define WQ4 (3 * HID * HID / 4)
#define WO4 (HID * HID / 4)

__global__ void cvt_all(const float4* __restrict__ x,
                        const float4* __restrict__ wq,
                        const float4* __restrict__ wo,
                        uint2* __restrict__ xh,
                        uint2* __restrict__ wqh,
                        uint2* __restrict__ woh) {
    int i = blockIdx.x * blockDim.x + threadIdx.x;
    const float4* src;
    uint2* dst;
    int j;
    if (i < X4)                  { src = x;  dst = xh;  j = i; }
    else if (i < X4 + WQ4)       { src = wq; dst = wqh; j = i - X4; }
    else if (i < X4 + WQ4 + WO4) { src = wo; dst = woh; j = i - X4 - WQ4; }
    else return;
    float4 v = src[j];
    __half2 a = __floats2half2_rn(v.x, v.y);
    __half2 b = __floats2half2_rn(v.z, v.w);
    uint2 o;
    o.x = *reinterpret_cast<uint32_t*>(&a);
    o.y = *reinterpret_cast<uint32_t*>(&b);
    dst[j] = o;
}

// ---------------------------------------------------------------------------
// mma.sync helpers
// ---------------------------------------------------------------------------
__device__ __forceinline__ void ldsm4(uint32_t* r, uint32_t addr) {
    asm volatile("ldmatrix.sync.aligned.m8n8.x4.shared.b16 {%0,%1,%2,%3},[%4];\n"
                 : "=r"(r[0]), "=r"(r[1]), "=r"(r[2]), "=r"(r[3]) : "r"(addr));
}
__device__ __forceinline__ void mma16816(float* d, const uint32_t* a, const uint32_t* b) {
    asm volatile("mma.sync.aligned.m16n8k16.row.col.f32.f16.f16.f32 "
                 "{%0,%1,%2,%3},{%4,%5,%6,%7},{%8,%9},{%0,%1,%2,%3};\n"
                 : "+f"(d[0]), "+f"(d[1]), "+f"(d[2]), "+f"(d[3])
                 : "r"(a[0]), "r"(a[1]), "r"(a[2]), "r"(a[3]),
                   "r"(b[0]), "r"(b[1]));
}
__device__ __forceinline__ void cp_async8(uint32_t saddr, const void* gaddr) {
    asm volatile("cp.async.ca.shared.global [%0], [%1], 8;\n"
                 :: "r"(saddr), "l"(gaddr) : "memory");
}

// smem per stage: A | B, each 128 rows x 40 halves (80 B rows, conflict-free)
#define GKP      40
#define GROW_B   (GKP * 2)              // 80 B per row
#define GMAT_B   (128 * GROW_B)         // 10240 B
#define GSTAGE_B (2 * GMAT_B)           // 20480 B
#define GSTAGES  4
#define GSMEM_B  (GSTAGES * GSTAGE_B)   // 81920 B

// ---------------------------------------------------------------------------
// fp16 tensor-core GEMM (NT): C[M,N] = A[M,K] * B[N,K]^T, fp32 accumulate.
// Tile 128x128, BK=32, 4-stage cp.async, ONE __syncthreads per chunk.
// Safety of single sync: at iter c we write stage (c+2)%4; readers are at
// stage c%4 (this iter) or (c+3)%4 (slow warps still in iter c-1) — disjoint.
// ---------------------------------------------------------------------------
template <typename OutT>
__global__ __launch_bounds__(256, 2)
void gemm_f16_pipe(const __half* __restrict__ A, const __half* __restrict__ B,
                   OutT* __restrict__ C, int M, int N, int K) {
    extern __shared__ __align__(16) char smem_raw[];
    const uint32_t sb = (uint32_t)__cvta_generic_to_shared(smem_raw);

    const int tid  = threadIdx.x;
    const int lane = tid & 31;
    const int warp = tid >> 5;
    const int wm = (warp >> 2) * 64;
    const int wn = (warp & 3) * 32;
    const int mrow0 = blockIdx.y * 128;
    const int ncol0 = blockIdx.x * 128;

    float acc[4][4][4];
#pragma unroll
    for (int mi = 0; mi < 4; mi++)
#pragma unroll
        for (int ni = 0; ni < 4; ni++)
#pragma unroll
            for (int r = 0; r < 4; r++) acc[mi][ni][r] = 0.0f;

    const __half* pA = A + (size_t)mrow0 * K;
    const __half* pB = B + (size_t)ncol0 * K;

    // hoisted loader offsets
    const int l_row = tid >> 3;          // 0..31  (x4 iters -> 128 rows)
    const int l_c   = tid & 7;
    const uint32_t l_soff = (uint32_t)(l_row * GROW_B + l_c * 8);
    const size_t   l_goff = (size_t)l_row * K + l_c * 4;

    auto load_stage = [&](int buf, int k0) {
        const uint32_t stage = sb + buf * GSTAGE_B;
#pragma unroll
        for (int it = 0; it < 4; it++) {
            const uint32_t so = stage + l_soff + (uint32_t)(it * 32 * GROW_B);
            const size_t   go = l_goff + (size_t)(it * 32) * K + k0;
            cp_async8(so, pA + go);
            cp_async8(so + GMAT_B, pB + go);
        }
        asm volatile("cp.async.commit_group;\n" ::: "memory");
    };

    // hoisted ldmatrix offsets
    const int a_row = (lane & 15);
    const int a_kof = (lane >> 4) << 3;
    const int b_loc = ((lane >> 3) & 1) * 8 + (lane & 7);
    const int b_kof = (lane >> 4) << 3;
    uint32_t aoff[4], boff[2];
#pragma unroll
    for (int mi = 0; mi < 4; mi++)
        aoff[mi] = (uint32_t)((wm + mi * 16 + a_row) * GROW_B + a_kof * 2);
#pragma unroll
    for (int p = 0; p < 2; p++)
        boff[p] = (uint32_t)(GMAT_B + (wn + p * 16 + b_loc) * GROW_B + b_kof * 2);

    const int nchunk = K / 32;
    load_stage(0, 0);
    load_stage(1, 32);

    for (int c = 0; c < nchunk; c++) {
        if (c + 2 < nchunk) {
            load_stage((c + 2) & 3, (c + 2) * 32);
            asm volatile("cp.async.wait_group 2;\n" ::: "memory");
        } else if (c + 1 < nchunk) {
            asm volatile("cp.async.wait_group 1;\n" ::: "memory");
        } else {
            asm volatile("cp.async.wait_group 0;\n" ::: "memory");
        }
        __syncthreads();

        const uint32_t stage = sb + (c & 3) * GSTAGE_B;
#pragma unroll
        for (int kk = 0; kk < 2; kk++) {
            const uint32_t ko = (uint32_t)(kk * 32);
            uint32_t a[4][4];
            uint32_t b[4][2];
#pragma unroll
            for (int mi = 0; mi < 4; mi++)
                ldsm4(a[mi], stage + aoff[mi] + ko);
#pragma unroll
            for (int p = 0; p < 2; p++) {
                uint32_t r[4];
                ldsm4(r, stage + boff[p] + ko);
                b[p * 2 + 0][0] = r[0]; b[p * 2 + 0][1] = r[2];
                b[p * 2 + 1][0] = r[1]; b[p * 2 + 1][1] = r[3];
            }
#pragma unroll
            for (int mi = 0; mi < 4; mi++)
#pragma unroll
                for (int ni = 0; ni < 4; ni++)
                    mma16816(acc[mi][ni], a[mi], b[ni]);
        }
    }
    __syncthreads();

    const int em = mrow0 + wm + (lane >> 2);
    const int en = ncol0 + wn + (lane & 3) * 2;
#pragma unroll
    for (int mi = 0; mi < 4; mi++) {
#pragma unroll
        for (int ni = 0; ni < 4; ni++) {
            if constexpr (std::is_same<OutT, __half>::value) {
                __half* c0 = C + (size_t)(em + mi * 16) * N + en + ni * 8;
                __half* c1 = C + (size_t)(em + mi * 16 + 8) * N + en + ni * 8;
                __half2 h0 = __floats2half2_rn(acc[mi][ni][0], acc[mi][ni][1]);
                __half2 h1 = __floats2half2_rn(acc[mi][ni][2], acc[mi][ni][3]);
                *reinterpret_cast<__half2*>(c0) = h0;
                *reinterpret_cast<__half2*>(c1) = h1;
            } else {
                float* c0 = C + (size_t)(em + mi * 16) * N + en + ni * 8;
                float* c1 = C + (size_t)(em + mi * 16 + 8) * N + en + ni * 8;
                *reinterpret_cast<float2*>(c0) = make_float2(acc[mi][ni][0], acc[mi][ni][1]);
                *reinterpret_cast<float2*>(c1) = make_float2(acc[mi][ni][2], acc[mi][ni][3]);
            }
        }
    }
}

// ---------------------------------------------------------------------------
// Smem-tiled local attention, fp16 in / fp16 out, fp32 arithmetic.
// Block = (4x4x4 token tile) x head x batch; 6x6x6 halo of k,v in fp16 smem.
// OOB halo rows are zero -> logit exactly 0 in softmax + value 0, matching
// the reference's zero-padding.
// ---------------------------------------------------------------------------
#define AT_HALO 216
#define KSTRH   68   // halves per halo row (64 + 4 pad; 136 B, 8B-aligned)
#define AT_SMEM ((2 * AT_HALO * KSTRH + 64 * 64) * 2)

__global__ __launch_bounds__(256, 2)
void local_attn_f16(const __half* __restrict__ qkv, __half* __restrict__ att) {
    extern __shared__ __align__(16) __half smh[];
    __half* k_s = smh;
    __half* v_s = smh + AT_HALO * KSTRH;
    __half* q_s = v_s + AT_HALO * KSTRH;

    const int tile = blockIdx.x;
    const int head = blockIdx.y;
    const int b    = blockIdx.z;
    const int t0 = (tile >> 4) * 4;
    const int h0 = ((tile >> 2) & 3) * 4;
    const int w0 = (tile & 3) * 4;
    const int tid = threadIdx.x;

    // halo load: 216 tokens x 16 chunks of 8B (4 halves) for k and v
    for (int idx = tid; idx < AT_HALO * 16; idx += 256) {
        const int tok = idx >> 4;
        const int c8  = idx & 15;
        const int ht = tok / 36, hh = (tok / 6) % 6, hw = tok % 6;
        const int gt = t0 - 1 + ht, gh = h0 - 1 + hh, gw = w0 - 1 + hw;
        uint2 kv = make_uint2(0u, 0u), vv = make_uint2(0u, 0u);
        if (gt >= 0 && gt < TOKEN_T && gh >= 0 && gh < TOKEN_HH &&
            gw >= 0 && gw < TOKEN_WW) {
            const int n = (gt * TOKEN_HH + gh) * TOKEN_WW + gw;
            const __half* base = qkv + ((size_t)(b * NTOK + n)) * (3 * HID) + head * HDIM + c8 * 4;
            kv = *reinterpret_cast<const uint2*>(base + HID);
            vv = *reinterpret_cast<const uint2*>(base + 2 * HID);
        }
        *reinterpret_cast<uint2*>(&k_s[tok * KSTRH + c8 * 4]) = kv;
        *reinterpret_cast<uint2*>(&v_s[tok * KSTRH + c8 * 4]) = vv;
    }
    // q load: 64 tokens x 16 chunks of 8B
    for (int idx = tid; idx < 64 * 16; idx += 256) {
        const int tok = idx >> 4, c8 = idx & 15;
        const int lt = tok >> 4, lh = (tok >> 2) & 3, lw = tok & 3;
        const int n = ((t0 + lt) * TOKEN_HH + (h0 + lh)) * TOKEN_WW + (w0 + lw);
        uint2 qv = *reinterpret_cast<const uint2*>(
            qkv + ((size_t)(b * NTOK + n)) * (3 * HID) + head * HDIM + c8 * 4);
        *reinterpret_cast<uint2*>(&q_s[tok * 64 + c8 * 4]) = qv;
    }
    __syncthreads();

    const int warp = tid >> 5, lane = tid & 31;
#pragma unroll
    for (int i = 0; i < 8; i++) {
        const int tok = warp * 8 + i;
        const int lt = tok >> 4, lh = (tok >> 2) & 3, lw = tok & 3;

        float s = 0.f;
        int hrow = 0;
        if (lane < 27) {
            const int dt = lane / 9, dh = (lane / 3) % 3, dw = lane % 3;
            hrow = ((lt + dt) * 6 + (lh + dh)) * 6 + (lw + dw);
            const __half2* kp = reinterpret_cast<const __half2*>(&k_s[hrow * KSTRH]);
            const __half2* qp = reinterpret_cast<const __half2*>(&q_s[tok * 64]);
#pragma unroll
            for (int d = 0; d < 32; d++) {
                const float2 kk2 = __half22float2(kp[d]);
                const float2 qq2 = __half22float2(qp[d]);
                s = fmaf(qq2.x, kk2.x, s);
                s = fmaf(qq2.y, kk2.y, s);
            }
            s *= 0.125f;
        }
        float sl = (lane < 27) ? s : -1e30f;
#pragma unroll
        for (int off = 16; off; off >>= 1)
            sl = fmaxf(sl, __shfl_xor_sync(0xffffffffu, sl, off));
        const float e = (lane < 27) ? __expf(s - sl) : 0.f;
        float den = e;
#pragma unroll
        for (int off = 16; off; off >>= 1)
            den += __shfl_xor_sync(0xffffffffu, den, off);
        const float w = e / den;

        float o0 = 0.f, o1 = 0.f;
#pragma unroll
        for (int j = 0; j < 27; j++) {
            const float wj = __shfl_sync(0xffffffffu, w, j);
            const int   rj = __shfl_sync(0xffffffffu, hrow, j);
            o0 = fmaf(wj, __half2float(v_s[rj * KSTRH + lane]), o0);
            o1 = fmaf(wj, __half2float(v_s[rj * KSTRH + lane + 32]), o1);
        }
        const int n = ((t0 + lt) * TOKEN_HH + (h0 + lh)) * TOKEN_WW + (w0 + lw);
        __half* op = att + ((size_t)(b * NTOK + n)) * HID + head * HDIM;
        op[lane]      = __float2half_rn(o0);
        op[lane + 32] = __float2half_rn(o1);
    }
}

// ---------------------------------------------------------------------------
// Launch
// ---------------------------------------------------------------------------
extern "C" void kernel_launch(void* const* d_in, const int* in_sizes, int n_in,
                              void* d_out, int out_size) {
    const float* x     = (const float*)d_in[0];
    const float* w_qkv = (const float*)d_in[1];
    const float* w_out = (const float*)d_in[2];
    float* out = (float*)d_out;

    __half *qkvh, *xh, *wqh, *woh, *atth;
    cudaGetSymbolAddress((void**)&qkvh, g_qkvh);
    cudaGetSymbolAddress((void**)&xh, g_xh);
    cudaGetSymbolAddress((void**)&wqh, g_wqh);
    cudaGetSymbolAddress((void**)&woh, g_woh);
    cudaGetSymbolAddress((void**)&atth, g_atth);

    cudaFuncSetAttribute(gemm_f16_pipe<__half>,
                         cudaFuncAttributeMaxDynamicSharedMemorySize, GSMEM_B);
    cudaFuncSetAttribute(gemm_f16_pipe<float>,
                         cudaFuncAttributeMaxDynamicSharedMemorySize, GSMEM_B);
    cudaFuncSetAttribute(local_attn_f16,
                         cudaFuncAttributeMaxDynamicSharedMemorySize, AT_SMEM);

    // 0) fused conversions
    {
        const int total = X4 + WQ4 + WO4;
        cvt_all<<<(total + 255) / 256, 256>>>((const float4*)x, (const float4*)w_qkv,
                                              (const float4*)w_out,
                                              (uint2*)xh, (uint2*)wqh, (uint2*)woh);
    }

    // 1) QKV: (4096,3072) = x * w_qkv^T -> fp16
    {
        dim3 grid(3 * HID / 128, M_TOT / 128);
        gemm_f16_pipe<__half><<<grid, 256, GSMEM_B>>>(xh, wqh, qkvh, M_TOT, 3 * HID, HID);
    }

    // 2) local attention (fp16 in/out)
    {
        dim3 grid(32, NHEAD, BATCH);
        local_attn_f16<<<grid, 256, AT_SMEM>>>(qkvh, atth);
    }

    // 3) out-proj: (4096,1024) = att * w_out^T -> fp32 output
    {
        dim3 grid(HID / 128, M_TOT / 128);
        gemm_f16_pipe<float><<<grid, 256, GSMEM_B>>>(atth, woh, out, M_TOT, HID, HID);
    }
}

// round 7
// speedup vs baseline: 5.1337x; 1.0446x over previous
#include <cuda_runtime.h>
#include <cuda_fp16.h>
#include <cstdint>
#include <type_traits>

// ---------------------------------------------------------------------------
// LocalAttention: x(2,2048,1024) -> qkv gemm -> 27-neighbor local attention
//                 (8x16x16 grid, 16 heads x 64 dim) -> out-proj gemm.
// Round 7: fp16 GEMM with 256x128 block tile / 64x64 warp tile (halves smem
//          read amplification), 4-stage cp.async, fragment double-buffering.
// ---------------------------------------------------------------------------

#define TOKEN_T  8
#define TOKEN_HH 16
#define TOKEN_WW 16
#define NTOK     2048
#define BATCH    2
#define HID      1024
#define NHEAD    16
#define HDIM     64
#define M_TOT    (BATCH * NTOK)   // 4096

// Scratch (device globals: allocation-free per harness rules)
__device__ __half g_qkvh[(size_t)M_TOT * 3 * HID];
__device__ __half g_xh[(size_t)M_TOT * HID];
__device__ __half g_wqh[(size_t)3 * HID * HID];
__device__ __half g_woh[(size_t)HID * HID];
__device__ __half g_atth[(size_t)M_TOT * HID];

// ---------------------------------------------------------------------------
// Fused fp32 -> fp16 conversion of x, w_qkv, w_out in one launch.
// ---------------------------------------------------------------------------
#define X4  (M_TOT * HID / 4)
#define WQ4 (3 * HID * HID / 4)
#define WO4 (HID * HID / 4)

__global__ void cvt_all(const float4* __restrict__ x,
                        const float4* __restrict__ wq,
                        const float4* __restrict__ wo,
                        uint2* __restrict__ xh,
                        uint2* __restrict__ wqh,
                        uint2* __restrict__ woh) {
    int i = blockIdx.x * blockDim.x + threadIdx.x;
    const float4* src;
    uint2* dst;
    int j;
    if (i < X4)                  { src = x;  dst = xh;  j = i; }
    else if (i < X4 + WQ4)       { src = wq; dst = wqh; j = i - X4; }
    else if (i < X4 + WQ4 + WO4) { src = wo; dst = woh; j = i - X4 - WQ4; }
    else return;
    float4 v = src[j];
    __half2 a = __floats2half2_rn(v.x, v.y);
    __half2 b = __floats2half2_rn(v.z, v.w);
    uint2 o;
    o.x = *reinterpret_cast<uint32_t*>(&a);
    o.y = *reinterpret_cast<uint32_t*>(&b);
    dst[j] = o;
}

// ---------------------------------------------------------------------------
// mma.sync helpers
// ---------------------------------------------------------------------------
__device__ __forceinline__ void ldsm4(uint32_t* r, uint32_t addr) {
    asm volatile("ldmatrix.sync.aligned.m8n8.x4.shared.b16 {%0,%1,%2,%3},[%4];\n"
                 : "=r"(r[0]), "=r"(r[1]), "=r"(r[2]), "=r"(r[3]) : "r"(addr));
}
__device__ __forceinline__ void mma16816(float* d, const uint32_t* a, const uint32_t* b) {
    asm volatile("mma.sync.aligned.m16n8k16.row.col.f32.f16.f16.f32 "
                 "{%0,%1,%2,%3},{%4,%5,%6,%7},{%8,%9},{%0,%1,%2,%3};\n"
                 : "+f"(d[0]), "+f"(d[1]), "+f"(d[2]), "+f"(d[3])
                 : "r"(a[0]), "r"(a[1]), "r"(a[2]), "r"(a[3]),
                   "r"(b[0]), "r"(b[1]));
}
__device__ __forceinline__ void cp_async8(uint32_t saddr, const void* gaddr) {
    asm volatile("cp.async.ca.shared.global [%0], [%1], 8;\n"
                 :: "r"(saddr), "l"(gaddr) : "memory");
}

// smem: per stage A(256 rows) | B(128 rows), 40 halves per row (80B, pad-free
// for conflict-free ldmatrix)
#define GROW_B   80                      // bytes per row
#define AMAT_B   (256 * GROW_B)          // 20480 B
#define BMAT_B   (128 * GROW_B)          // 10240 B
#define GSTAGE_B (AMAT_B + BMAT_B)       // 30720 B
#define GSTAGES  4
#define GSMEM_B  (GSTAGES * GSTAGE_B)    // 122880 B

// ---------------------------------------------------------------------------
// fp16 tensor-core GEMM (NT): C[M,N] = A[M,K] * B[N,K]^T, fp32 accumulate.
// Block tile 256x128, BK=32, 8 warps with 64x64 warp tiles (warp grid 4Mx2N),
// 4-stage cp.async, fragment double-buffering across the 2 kk-steps.
// Requires M%256==0, N%128==0, K%32==0.
// ---------------------------------------------------------------------------
template <typename OutT>
__global__ __launch_bounds__(256, 1)
void gemm_f16_pipe(const __half* __restrict__ A, const __half* __restrict__ B,
                   OutT* __restrict__ C, int M, int N, int K) {
    extern __shared__ __align__(16) char smem_raw[];
    const uint32_t sb = (uint32_t)__cvta_generic_to_shared(smem_raw);

    const int tid  = threadIdx.x;
    const int lane = tid & 31;
    const int warp = tid >> 5;
    const int wm = (warp & 3) * 64;    // warp M offset (4 warps down M)
    const int wn = (warp >> 2) * 64;   // warp N offset (2 warps across N)
    const int mrow0 = blockIdx.y * 256;
    const int ncol0 = blockIdx.x * 128;

    float acc[4][8][4];
#pragma unroll
    for (int mi = 0; mi < 4; mi++)
#pragma unroll
        for (int ni = 0; ni < 8; ni++)
#pragma unroll
            for (int r = 0; r < 4; r++) acc[mi][ni][r] = 0.0f;

    const __half* pA = A + (size_t)mrow0 * K;
    const __half* pB = B + (size_t)ncol0 * K;

    // loader: A = 2048 8B-chunks (8/thread), B = 1024 (4/thread)
    const int l_row = tid >> 3;          // 0..31
    const int l_c   = tid & 7;
    const uint32_t l_soff = (uint32_t)(l_row * GROW_B + l_c * 8);
    const size_t   l_goff = (size_t)l_row * K + l_c * 4;

    auto load_stage = [&](int buf, int k0) {
        const uint32_t stage = sb + buf * GSTAGE_B;
#pragma unroll
        for (int it = 0; it < 8; it++)
            cp_async8(stage + l_soff + (uint32_t)(it * 32 * GROW_B),
                      pA + l_goff + (size_t)(it * 32) * K + k0);
#pragma unroll
        for (int it = 0; it < 4; it++)
            cp_async8(stage + AMAT_B + l_soff + (uint32_t)(it * 32 * GROW_B),
                      pB + l_goff + (size_t)(it * 32) * K + k0);
        asm volatile("cp.async.commit_group;\n" ::: "memory");
    };

    // ldmatrix lane geometry (16-row x4 loads)
    const int a_row = (lane & 15);
    const int a_kof = (lane >> 4) << 3;
    const int b_loc = ((lane >> 3) & 1) * 8 + (lane & 7);
    const int b_kof = (lane >> 4) << 3;
    uint32_t aoff[4], boff[4];
#pragma unroll
    for (int mi = 0; mi < 4; mi++)
        aoff[mi] = (uint32_t)((wm + mi * 16 + a_row) * GROW_B + a_kof * 2);
#pragma unroll
    for (int p = 0; p < 4; p++)
        boff[p] = (uint32_t)(AMAT_B + (wn + p * 16 + b_loc) * GROW_B + b_kof * 2);

    uint32_t afr[2][4][4];
    uint32_t bfr[2][8][2];

    auto ld_frags = [&](int fb, uint32_t stage, uint32_t ko) {
#pragma unroll
        for (int mi = 0; mi < 4; mi++)
            ldsm4(afr[fb][mi], stage + aoff[mi] + ko);
#pragma unroll
        for (int p = 0; p < 4; p++) {
            uint32_t r[4];
            ldsm4(r, stage + boff[p] + ko);
            bfr[fb][p * 2 + 0][0] = r[0]; bfr[fb][p * 2 + 0][1] = r[2];
            bfr[fb][p * 2 + 1][0] = r[1]; bfr[fb][p * 2 + 1][1] = r[3];
        }
    };

    const int nchunk = K / 32;
    load_stage(0, 0);
    load_stage(1, 32);

    for (int c = 0; c < nchunk; c++) {
        if (c + 2 < nchunk) {
            load_stage((c + 2) & 3, (c + 2) * 32);
            asm volatile("cp.async.wait_group 2;\n" ::: "memory");
        } else if (c + 1 < nchunk) {
            asm volatile("cp.async.wait_group 1;\n" ::: "memory");
        } else {
            asm volatile("cp.async.wait_group 0;\n" ::: "memory");
        }
        __syncthreads();

        const uint32_t stage = sb + (c & 3) * GSTAGE_B;
        ld_frags(0, stage, 0);
#pragma unroll
        for (int kk = 0; kk < 2; kk++) {
            if (kk == 0) ld_frags(1, stage, 32);
#pragma unroll
            for (int mi = 0; mi < 4; mi++)
#pragma unroll
                for (int ni = 0; ni < 8; ni++)
                    mma16816(acc[mi][ni], afr[kk][mi], bfr[kk][ni]);
        }
    }
    __syncthreads();

    const int em = mrow0 + wm + (lane >> 2);
    const int en = ncol0 + wn + (lane & 3) * 2;
#pragma unroll
    for (int mi = 0; mi < 4; mi++) {
#pragma unroll
        for (int ni = 0; ni < 8; ni++) {
            if constexpr (std::is_same<OutT, __half>::value) {
                __half* c0 = C + (size_t)(em + mi * 16) * N + en + ni * 8;
                __half* c1 = C + (size_t)(em + mi * 16 + 8) * N + en + ni * 8;
                *reinterpret_cast<__half2*>(c0) = __floats2half2_rn(acc[mi][ni][0], acc[mi][ni][1]);
                *reinterpret_cast<__half2*>(c1) = __floats2half2_rn(acc[mi][ni][2], acc[mi][ni][3]);
            } else {
                float* c0 = C + (size_t)(em + mi * 16) * N + en + ni * 8;
                float* c1 = C + (size_t)(em + mi * 16 + 8) * N + en + ni * 8;
                *reinterpret_cast<float2*>(c0) = make_float2(acc[mi][ni][0], acc[mi][ni][1]);
                *reinterpret_cast<float2*>(c1) = make_float2(acc[mi][ni][2], acc[mi][ni][3]);
            }
        }
    }
}

// ---------------------------------------------------------------------------
// Smem-tiled local attention, fp16 in / fp16 out, fp32 arithmetic.
// OOB halo rows are zero -> logit exactly 0 in softmax + value 0, matching
// the reference's zero-padding.
// ---------------------------------------------------------------------------
#define AT_HALO 216
#define KSTRH   68
#define AT_SMEM ((2 * AT_HALO * KSTRH + 64 * 64) * 2)

__global__ __launch_bounds__(256, 2)
void local_attn_f16(const __half* __restrict__ qkv, __half* __restrict__ att) {
    extern __shared__ __align__(16) __half smh[];
    __half* k_s = smh;
    __half* v_s = smh + AT_HALO * KSTRH;
    __half* q_s = v_s + AT_HALO * KSTRH;

    const int tile = blockIdx.x;
    const int head = blockIdx.y;
    const int b    = blockIdx.z;
    const int t0 = (tile >> 4) * 4;
    const int h0 = ((tile >> 2) & 3) * 4;
    const int w0 = (tile & 3) * 4;
    const int tid = threadIdx.x;

    for (int idx = tid; idx < AT_HALO * 16; idx += 256) {
        const int tok = idx >> 4;
        const int c8  = idx & 15;
        const int ht = tok / 36, hh = (tok / 6) % 6, hw = tok % 6;
        const int gt = t0 - 1 + ht, gh = h0 - 1 + hh, gw = w0 - 1 + hw;
        uint2 kv = make_uint2(0u, 0u), vv = make_uint2(0u, 0u);
        if (gt >= 0 && gt < TOKEN_T && gh >= 0 && gh < TOKEN_HH &&
            gw >= 0 && gw < TOKEN_WW) {
            const int n = (gt * TOKEN_HH + gh) * TOKEN_WW + gw;
            const __half* base = qkv + ((size_t)(b * NTOK + n)) * (3 * HID) + head * HDIM + c8 * 4;
            kv = *reinterpret_cast<const uint2*>(base + HID);
            vv = *reinterpret_cast<const uint2*>(base + 2 * HID);
        }
        *reinterpret_cast<uint2*>(&k_s[tok * KSTRH + c8 * 4]) = kv;
        *reinterpret_cast<uint2*>(&v_s[tok * KSTRH + c8 * 4]) = vv;
    }
    for (int idx = tid; idx < 64 * 16; idx += 256) {
        const int tok = idx >> 4, c8 = idx & 15;
        const int lt = tok >> 4, lh = (tok >> 2) & 3, lw = tok & 3;
        const int n = ((t0 + lt) * TOKEN_HH + (h0 + lh)) * TOKEN_WW + (w0 + lw);
        uint2 qv = *reinterpret_cast<const uint2*>(
            qkv + ((size_t)(b * NTOK + n)) * (3 * HID) + head * HDIM + c8 * 4);
        *reinterpret_cast<uint2*>(&q_s[tok * 64 + c8 * 4]) = qv;
    }
    __syncthreads();

    const int warp = tid >> 5, lane = tid & 31;
#pragma unroll
    for (int i = 0; i < 8; i++) {
        const int tok = warp * 8 + i;
        const int lt = tok >> 4, lh = (tok >> 2) & 3, lw = tok & 3;

        float s = 0.f;
        int hrow = 0;
        if (lane < 27) {
            const int dt = lane / 9, dh = (lane / 3) % 3, dw = lane % 3;
            hrow = ((lt + dt) * 6 + (lh + dh)) * 6 + (lw + dw);
            const __half2* kp = reinterpret_cast<const __half2*>(&k_s[hrow * KSTRH]);
            const __half2* qp = reinterpret_cast<const __half2*>(&q_s[tok * 64]);
#pragma unroll
            for (int d = 0; d < 32; d++) {
                const float2 kk2 = __half22float2(kp[d]);
                const float2 qq2 = __half22float2(qp[d]);
                s = fmaf(qq2.x, kk2.x, s);
                s = fmaf(qq2.y, kk2.y, s);
            }
            s *= 0.125f;
        }
        float sl = (lane < 27) ? s : -1e30f;
#pragma unroll
        for (int off = 16; off; off >>= 1)
            sl = fmaxf(sl, __shfl_xor_sync(0xffffffffu, sl, off));
        const float e = (lane < 27) ? __expf(s - sl) : 0.f;
        float den = e;
#pragma unroll
        for (int off = 16; off; off >>= 1)
            den += __shfl_xor_sync(0xffffffffu, den, off);
        const float w = e / den;

        float o0 = 0.f, o1 = 0.f;
#pragma unroll
        for (int j = 0; j < 27; j++) {
            const float wj = __shfl_sync(0xffffffffu, w, j);
            const int   rj = __shfl_sync(0xffffffffu, hrow, j);
            o0 = fmaf(wj, __half2float(v_s[rj * KSTRH + lane]), o0);
            o1 = fmaf(wj, __half2float(v_s[rj * KSTRH + lane + 32]), o1);
        }
        const int n = ((t0 + lt) * TOKEN_HH + (h0 + lh)) * TOKEN_WW + (w0 + lw);
        __half* op = att + ((size_t)(b * NTOK + n)) * HID + head * HDIM;
        op[lane]      = __float2half_rn(o0);
        op[lane + 32] = __float2half_rn(o1);
    }
}

// ---------------------------------------------------------------------------
// Launch
// ---------------------------------------------------------------------------
extern "C" void kernel_launch(void* const* d_in, const int* in_sizes, int n_in,
                              void* d_out, int out_size) {
    const float* x     = (const float*)d_in[0];
    const float* w_qkv = (const float*)d_in[1];
    const float* w_out = (const float*)d_in[2];
    float* out = (float*)d_out;

    __half *qkvh, *xh, *wqh, *woh, *atth;
    cudaGetSymbolAddress((void**)&qkvh, g_qkvh);
    cudaGetSymbolAddress((void**)&xh, g_xh);
    cudaGetSymbolAddress((void**)&wqh, g_wqh);
    cudaGetSymbolAddress((void**)&woh, g_woh);
    cudaGetSymbolAddress((void**)&atth, g_atth);

    cudaFuncSetAttribute(gemm_f16_pipe<__half>,
                         cudaFuncAttributeMaxDynamicSharedMemorySize, GSMEM_B);
    cudaFuncSetAttribute(gemm_f16_pipe<float>,
                         cudaFuncAttributeMaxDynamicSharedMemorySize, GSMEM_B);
    cudaFuncSetAttribute(local_attn_f16,
                         cudaFuncAttributeMaxDynamicSharedMemorySize, AT_SMEM);

    // 0) fused conversions
    {
        const int total = X4 + WQ4 + WO4;
        cvt_all<<<(total + 255) / 256, 256>>>((const float4*)x, (const float4*)w_qkv,
                                              (const float4*)w_out,
                                              (uint2*)xh, (uint2*)wqh, (uint2*)woh);
    }

    // 1) QKV: (4096,3072) = x * w_qkv^T -> fp16
    {
        dim3 grid(3 * HID / 128, M_TOT / 256);
        gemm_f16_pipe<__half><<<grid, 256, GSMEM_B>>>(xh, wqh, qkvh, M_TOT, 3 * HID, HID);
    }

    // 2) local attention (fp16 in/out)
    {
        dim3 grid(32, NHEAD, BATCH);
        local_attn_f16<<<grid, 256, AT_SMEM>>>(qkvh, atth);
    }

    // 3) out-proj: (4096,1024) = att * w_out^T -> fp32 output
    {
        dim3 grid(HID / 128, M_TOT / 256);
        gemm_f16_pipe<float><<<grid, 256, GSMEM_B>>>(atth, woh, out, M_TOT, HID, HID);
    }
}

// round 8
// speedup vs baseline: 5.4291x; 1.0575x over previous
#include <cuda_runtime.h>
#include <cuda_fp16.h>
#include <cstdint>
#include <type_traits>

// ---------------------------------------------------------------------------
// LocalAttention: x(2,2048,1024) -> qkv gemm -> 27-neighbor local attention
//                 (8x16x16 grid, 16 heads x 64 dim) -> out-proj gemm.
// Round 8: GEMM with 6-stage cp.async ring, sync every 2 chunks (prefetch
//          distance 3); attention with shuffle-free neighbor indexing + ILP.
// ---------------------------------------------------------------------------

#define TOKEN_T  8
#define TOKEN_HH 16
#define TOKEN_WW 16
#define NTOK     2048
#define BATCH    2
#define HID      1024
#define NHEAD    16
#define HDIM     64
#define M_TOT    (BATCH * NTOK)   // 4096

// Scratch (device globals: allocation-free per harness rules)
__device__ __half g_qkvh[(size_t)M_TOT * 3 * HID];
__device__ __half g_xh[(size_t)M_TOT * HID];
__device__ __half g_wqh[(size_t)3 * HID * HID];
__device__ __half g_woh[(size_t)HID * HID];
__device__ __half g_atth[(size_t)M_TOT * HID];

// ---------------------------------------------------------------------------
// Fused fp32 -> fp16 conversion of x, w_qkv, w_out in one launch.
// ---------------------------------------------------------------------------
#define X4  (M_TOT * HID / 4)
#define WQ4 (3 * HID * HID / 4)
#define WO4 (HID * HID / 4)

__global__ void cvt_all(const float4* __restrict__ x,
                        const float4* __restrict__ wq,
                        const float4* __restrict__ wo,
                        uint2* __restrict__ xh,
                        uint2* __restrict__ wqh,
                        uint2* __restrict__ woh) {
    int i = blockIdx.x * blockDim.x + threadIdx.x;
    const float4* src;
    uint2* dst;
    int j;
    if (i < X4)                  { src = x;  dst = xh;  j = i; }
    else if (i < X4 + WQ4)       { src = wq; dst = wqh; j = i - X4; }
    else if (i < X4 + WQ4 + WO4) { src = wo; dst = woh; j = i - X4 - WQ4; }
    else return;
    float4 v = src[j];
    __half2 a = __floats2half2_rn(v.x, v.y);
    __half2 b = __floats2half2_rn(v.z, v.w);
    uint2 o;
    o.x = *reinterpret_cast<uint32_t*>(&a);
    o.y = *reinterpret_cast<uint32_t*>(&b);
    dst[j] = o;
}

// ---------------------------------------------------------------------------
// mma.sync helpers
// ---------------------------------------------------------------------------
__device__ __forceinline__ void ldsm4(uint32_t* r, uint32_t addr) {
    asm volatile("ldmatrix.sync.aligned.m8n8.x4.shared.b16 {%0,%1,%2,%3},[%4];\n"
                 : "=r"(r[0]), "=r"(r[1]), "=r"(r[2]), "=r"(r[3]) : "r"(addr));
}
__device__ __forceinline__ void mma16816(float* d, const uint32_t* a, const uint32_t* b) {
    asm volatile("mma.sync.aligned.m16n8k16.row.col.f32.f16.f16.f32 "
                 "{%0,%1,%2,%3},{%4,%5,%6,%7},{%8,%9},{%0,%1,%2,%3};\n"
                 : "+f"(d[0]), "+f"(d[1]), "+f"(d[2]), "+f"(d[3])
                 : "r"(a[0]), "r"(a[1]), "r"(a[2]), "r"(a[3]),
                   "r"(b[0]), "r"(b[1]));
}
__device__ __forceinline__ void cp_async8(uint32_t saddr, const void* gaddr) {
    asm volatile("cp.async.ca.shared.global [%0], [%1], 8;\n"
                 :: "r"(saddr), "l"(gaddr) : "memory");
}

// smem: per stage A(256 rows) | B(128 rows), 40 halves/row (80B, conflict-free)
#define GROW_B   80
#define AMAT_B   (256 * GROW_B)          // 20480 B
#define BMAT_B   (128 * GROW_B)          // 10240 B
#define GSTAGE_B (AMAT_B + BMAT_B)       // 30720 B
#define GSTAGES  6
#define GSMEM_B  (GSTAGES * GSTAGE_B)    // 184320 B

// ---------------------------------------------------------------------------
// fp16 tensor-core GEMM (NT): C[M,N] = A[M,K] * B[N,K]^T, fp32 accumulate.
// Block tile 256x128, BK=32, 8 warps (64x64 warp tiles), 6-stage cp.async,
// barrier + wait every 2 chunks (prefetch distance 3).
// Safety: barrier at even chunk cb bounds all readers to {cb-1, cb}; writes at
// iter c go to stage (c+3)%6, disjoint from (c-1)%6 and c%6 mod 6. The even-c
// wait_group 2 leaves only {c+2, c+3} pending -> stages c and c+1 complete
// before the barrier that covers both chunks.
// ---------------------------------------------------------------------------
template <typename OutT>
__global__ __launch_bounds__(256, 1)
void gemm_f16_pipe(const __half* __restrict__ A, const __half* __restrict__ B,
                   OutT* __restrict__ C, int M, int N, int K) {
    extern __shared__ __align__(16) char smem_raw[];
    const uint32_t sb = (uint32_t)__cvta_generic_to_shared(smem_raw);

    const int tid  = threadIdx.x;
    const int lane = tid & 31;
    const int warp = tid >> 5;
    const int wm = (warp & 3) * 64;
    const int wn = (warp >> 2) * 64;
    const int mrow0 = blockIdx.y * 256;
    const int ncol0 = blockIdx.x * 128;

    float acc[4][8][4];
#pragma unroll
    for (int mi = 0; mi < 4; mi++)
#pragma unroll
        for (int ni = 0; ni < 8; ni++)
#pragma unroll
            for (int r = 0; r < 4; r++) acc[mi][ni][r] = 0.0f;

    const __half* pA = A + (size_t)mrow0 * K;
    const __half* pB = B + (size_t)ncol0 * K;

    const int l_row = tid >> 3;
    const int l_c   = tid & 7;
    const uint32_t l_soff = (uint32_t)(l_row * GROW_B + l_c * 8);
    const size_t   l_goff = (size_t)l_row * K + l_c * 4;

    auto load_stage = [&](int buf, int k0) {
        const uint32_t stage = sb + buf * GSTAGE_B;
#pragma unroll
        for (int it = 0; it < 8; it++)
            cp_async8(stage + l_soff + (uint32_t)(it * 32 * GROW_B),
                      pA + l_goff + (size_t)(it * 32) * K + k0);
#pragma unroll
        for (int it = 0; it < 4; it++)
            cp_async8(stage + AMAT_B + l_soff + (uint32_t)(it * 32 * GROW_B),
                      pB + l_goff + (size_t)(it * 32) * K + k0);
        asm volatile("cp.async.commit_group;\n" ::: "memory");
    };

    const int a_row = (lane & 15);
    const int a_kof = (lane >> 4) << 3;
    const int b_loc = ((lane >> 3) & 1) * 8 + (lane & 7);
    const int b_kof = (lane >> 4) << 3;
    uint32_t aoff[4], boff[4];
#pragma unroll
    for (int mi = 0; mi < 4; mi++)
        aoff[mi] = (uint32_t)((wm + mi * 16 + a_row) * GROW_B + a_kof * 2);
#pragma unroll
    for (int p = 0; p < 4; p++)
        boff[p] = (uint32_t)(AMAT_B + (wn + p * 16 + b_loc) * GROW_B + b_kof * 2);

    uint32_t afr[2][4][4];
    uint32_t bfr[2][8][2];
    auto ld_frags = [&](int fb, uint32_t stage, uint32_t ko) {
#pragma unroll
        for (int mi = 0; mi < 4; mi++)
            ldsm4(afr[fb][mi], stage + aoff[mi] + ko);
#pragma unroll
        for (int p = 0; p < 4; p++) {
            uint32_t r[4];
            ldsm4(r, stage + boff[p] + ko);
            bfr[fb][p * 2 + 0][0] = r[0]; bfr[fb][p * 2 + 0][1] = r[2];
            bfr[fb][p * 2 + 1][0] = r[1]; bfr[fb][p * 2 + 1][1] = r[3];
        }
    };

    const int nchunk = K / 32;                 // 32 (even)
    load_stage(0, 0);
    load_stage(1, 32);
    load_stage(2, 64);

    for (int c = 0; c < nchunk; c++) {
        if (c + 3 < nchunk) load_stage((c + 3) % GSTAGES, (c + 3) * 32);
        if ((c & 1) == 0) {
            if (c + 3 < nchunk) {
                asm volatile("cp.async.wait_group 2;\n" ::: "memory");
            } else {
                asm volatile("cp.async.wait_group 0;\n" ::: "memory");
            }
            __syncthreads();
        }
        const uint32_t stage = sb + (c % GSTAGES) * GSTAGE_B;
        ld_frags(0, stage, 0);
#pragma unroll
        for (int kk = 0; kk < 2; kk++) {
            if (kk == 0) ld_frags(1, stage, 32);
#pragma unroll
            for (int mi = 0; mi < 4; mi++)
#pragma unroll
                for (int ni = 0; ni < 8; ni++)
                    mma16816(acc[mi][ni], afr[kk][mi], bfr[kk][ni]);
        }
    }

    const int em = mrow0 + wm + (lane >> 2);
    const int en = ncol0 + wn + (lane & 3) * 2;
#pragma unroll
    for (int mi = 0; mi < 4; mi++) {
#pragma unroll
        for (int ni = 0; ni < 8; ni++) {
            if constexpr (std::is_same<OutT, __half>::value) {
                __half* c0 = C + (size_t)(em + mi * 16) * N + en + ni * 8;
                __half* c1 = C + (size_t)(em + mi * 16 + 8) * N + en + ni * 8;
                *reinterpret_cast<__half2*>(c0) = __floats2half2_rn(acc[mi][ni][0], acc[mi][ni][1]);
                *reinterpret_cast<__half2*>(c1) = __floats2half2_rn(acc[mi][ni][2], acc[mi][ni][3]);
            } else {
                float* c0 = C + (size_t)(em + mi * 16) * N + en + ni * 8;
                float* c1 = C + (size_t)(em + mi * 16 + 8) * N + en + ni * 8;
                *reinterpret_cast<float2*>(c0) = make_float2(acc[mi][ni][0], acc[mi][ni][1]);
                *reinterpret_cast<float2*>(c1) = make_float2(acc[mi][ni][2], acc[mi][ni][3]);
            }
        }
    }
}

// ---------------------------------------------------------------------------
// Smem-tiled local attention, fp16 in/out, fp32 math.
// OOB halo rows are zero -> logit exactly 0 in softmax + value 0, matching
// the reference's zero-padding.
// Neighbor rows rj = base + const_j (no shuffles for indices); dot has 4-way
// ILP; only weight broadcast uses shfl (27 per token).
// ---------------------------------------------------------------------------
#define AT_HALO 216
#define KSTRH   68
#define AT_SMEM ((2 * AT_HALO * KSTRH + 64 * 64) * 2)

__global__ __launch_bounds__(256, 3)
void local_attn_f16(const __half* __restrict__ qkv, __half* __restrict__ att) {
    extern __shared__ __align__(16) __half smh[];
    __half* k_s = smh;
    __half* v_s = smh + AT_HALO * KSTRH;
    __half* q_s = v_s + AT_HALO * KSTRH;

    const int tile = blockIdx.x;
    const int head = blockIdx.y;
    const int b    = blockIdx.z;
    const int t0 = (tile >> 4) * 4;
    const int h0 = ((tile >> 2) & 3) * 4;
    const int w0 = (tile & 3) * 4;
    const int tid = threadIdx.x;

    for (int idx = tid; idx < AT_HALO * 16; idx += 256) {
        const int tok = idx >> 4;
        const int c8  = idx & 15;
        const int ht = tok / 36, hh = (tok / 6) % 6, hw = tok % 6;
        const int gt = t0 - 1 + ht, gh = h0 - 1 + hh, gw = w0 - 1 + hw;
        uint2 kv = make_uint2(0u, 0u), vv = make_uint2(0u, 0u);
        if (gt >= 0 && gt < TOKEN_T && gh >= 0 && gh < TOKEN_HH &&
            gw >= 0 && gw < TOKEN_WW) {
            const int n = (gt * TOKEN_HH + gh) * TOKEN_WW + gw;
            const __half* base = qkv + ((size_t)(b * NTOK + n)) * (3 * HID) + head * HDIM + c8 * 4;
            kv = *reinterpret_cast<const uint2*>(base + HID);
            vv = *reinterpret_cast<const uint2*>(base + 2 * HID);
        }
        *reinterpret_cast<uint2*>(&k_s[tok * KSTRH + c8 * 4]) = kv;
        *reinterpret_cast<uint2*>(&v_s[tok * KSTRH + c8 * 4]) = vv;
    }
    for (int idx = tid; idx < 64 * 16; idx += 256) {
        const int tok = idx >> 4, c8 = idx & 15;
        const int lt = tok >> 4, lh = (tok >> 2) & 3, lw = tok & 3;
        const int n = ((t0 + lt) * TOKEN_HH + (h0 + lh)) * TOKEN_WW + (w0 + lw);
        uint2 qv = *reinterpret_cast<const uint2*>(
            qkv + ((size_t)(b * NTOK + n)) * (3 * HID) + head * HDIM + c8 * 4);
        *reinterpret_cast<uint2*>(&q_s[tok * 64 + c8 * 4]) = qv;
    }
    __syncthreads();

    const int warp = tid >> 5, lane = tid & 31;
    // per-lane neighbor offset within the 6x6x6 halo (constant across tokens)
    const int doff = (lane < 27)
        ? (lane / 9) * 36 + ((lane / 3) % 3) * 6 + (lane % 3) : 0;

#pragma unroll
    for (int i = 0; i < 8; i++) {
        const int tok = warp * 8 + i;
        const int lt = tok >> 4, lh = (tok >> 2) & 3, lw = tok & 3;
        const int base = (lt * 6 + lh) * 6 + lw;   // halo row of (dt,dh,dw)=(0,0,0)... origin corner

        float s = 0.f;
        if (lane < 27) {
            const int hrow = base + doff;
            const __half2* kp = reinterpret_cast<const __half2*>(&k_s[hrow * KSTRH]);
            const __half2* qp = reinterpret_cast<const __half2*>(&q_s[tok * 64]);
            float s0 = 0.f, s1 = 0.f, s2 = 0.f, s3 = 0.f;
#pragma unroll
            for (int d = 0; d < 32; d += 4) {
                const float2 k0 = __half22float2(kp[d + 0]);
                const float2 q0 = __half22float2(qp[d + 0]);
                const float2 k1 = __half22float2(kp[d + 1]);
                const float2 q1 = __half22float2(qp[d + 1]);
                const float2 k2 = __half22float2(kp[d + 2]);
                const float2 q2 = __half22float2(qp[d + 2]);
                const float2 k3 = __half22float2(kp[d + 3]);
                const float2 q3 = __half22float2(qp[d + 3]);
                s0 = fmaf(q0.x, k0.x, s0); s0 = fmaf(q0.y, k0.y, s0);
                s1 = fmaf(q1.x, k1.x, s1); s1 = fmaf(q1.y, k1.y, s1);
                s2 = fmaf(q2.x, k2.x, s2); s2 = fmaf(q2.y, k2.y, s2);
                s3 = fmaf(q3.x, k3.x, s3); s3 = fmaf(q3.y, k3.y, s3);
            }
            s = ((s0 + s1) + (s2 + s3)) * 0.125f;
        }
        float sl = (lane < 27) ? s : -1e30f;
#pragma unroll
        for (int off = 16; off; off >>= 1)
            sl = fmaxf(sl, __shfl_xor_sync(0xffffffffu, sl, off));
        const float e = (lane < 27) ? __expf(s - sl) : 0.f;
        float den = e;
#pragma unroll
        for (int off = 16; off; off >>= 1)
            den += __shfl_xor_sync(0xffffffffu, den, off);
        const float w = e / den;

        float o0 = 0.f, o1 = 0.f;
#pragma unroll
        for (int j = 0; j < 27; j++) {
            const int rj = base + (j / 9) * 36 + ((j / 3) % 3) * 6 + (j % 3);
            const float wj = __shfl_sync(0xffffffffu, w, j);
            o0 = fmaf(wj, __half2float(v_s[rj * KSTRH + lane]), o0);
            o1 = fmaf(wj, __half2float(v_s[rj * KSTRH + lane + 32]), o1);
        }
        const int n = ((t0 + lt) * TOKEN_HH + (h0 + lh)) * TOKEN_WW + (w0 + lw);
        __half* op = att + ((size_t)(b * NTOK + n)) * HID + head * HDIM;
        op[lane]      = __float2half_rn(o0);
        op[lane + 32] = __float2half_rn(o1);
    }
}

// ---------------------------------------------------------------------------
// Launch
// ---------------------------------------------------------------------------
extern "C" void kernel_launch(void* const* d_in, const int* in_sizes, int n_in,
                              void* d_out, int out_size) {
    const float* x     = (const float*)d_in[0];
    const float* w_qkv = (const float*)d_in[1];
    const float* w_out = (const float*)d_in[2];
    float* out = (float*)d_out;

    __half *qkvh, *xh, *wqh, *woh, *atth;
    cudaGetSymbolAddress((void**)&qkvh, g_qkvh);
    cudaGetSymbolAddress((void**)&xh, g_xh);
    cudaGetSymbolAddress((void**)&wqh, g_wqh);
    cudaGetSymbolAddress((void**)&woh, g_woh);
    cudaGetSymbolAddress((void**)&atth, g_atth);

    cudaFuncSetAttribute(gemm_f16_pipe<__half>,
                         cudaFuncAttributeMaxDynamicSharedMemorySize, GSMEM_B);
    cudaFuncSetAttribute(gemm_f16_pipe<float>,
                         cudaFuncAttributeMaxDynamicSharedMemorySize, GSMEM_B);
    cudaFuncSetAttribute(local_attn_f16,
                         cudaFuncAttributeMaxDynamicSharedMemorySize, AT_SMEM);

    // 0) fused conversions
    {
        const int total = X4 + WQ4 + WO4;
        cvt_all<<<(total + 255) / 256, 256>>>((const float4*)x, (const float4*)w_qkv,
                                              (const float4*)w_out,
                                              (uint2*)xh, (uint2*)wqh, (uint2*)woh);
    }

    // 1) QKV: (4096,3072) = x * w_qkv^T -> fp16
    {
        dim3 grid(3 * HID / 128, M_TOT / 256);
        gemm_f16_pipe<__half><<<grid, 256, GSMEM_B>>>(xh, wqh, qkvh, M_TOT, 3 * HID, HID);
    }

    // 2) local attention (fp16 in/out)
    {
        dim3 grid(32, NHEAD, BATCH);
        local_attn_f16<<<grid, 256, AT_SMEM>>>(qkvh, atth);
    }

    // 3) out-proj: (4096,1024) = att * w_out^T -> fp32 output
    {
        dim3 grid(HID / 128, M_TOT / 256);
        gemm_f16_pipe<float><<<grid, 256, GSMEM_B>>>(atth, woh, out, M_TOT, HID, HID);
    }
}